// round 9
// baseline (speedup 1.0000x reference)
#include <cuda_runtime.h>
#include <cuda_fp16.h>
#include <cstdint>

// Problem constants (shapes fixed by the dataset)
#define N_NODES_MAX 100096
#define E_MAX       1600000
#define F 128
#define LIN_H 64
#define N_CLASSES 10
#define NUM_GRAPHS 64
#define SCAN_B 1024

// ---------------- scratch (device globals; zero-initialized at load) --------
// Invariant: every kernel_launch call leaves g_deg/g_cnt/g_flag/g_pool zeroed
// again (self-restoring), so graph replays are deterministic.
__device__ float        g_deg[N_NODES_MAX];
__device__ int          g_cnt[N_NODES_MAX];
__device__ int          g_start[N_NODES_MAX];
__device__ int          g_cursor[N_NODES_MAX];
__device__ float        g_dinv[N_NODES_MAX];
__device__ float2       g_csr[E_MAX];                         // (src as int bits, coef)
__device__ __half       g_xh[(size_t)N_NODES_MAX * F];        // 25.6 MB fp16 copy of x
__device__ __half       g_aggh[(size_t)N_NODES_MAX * F];      // 25.6 MB fp16 agg
__device__ unsigned int g_pool[NUM_GRAPHS * F];               // float-as-uint max
// decoupled-lookback scan state
__device__ volatile int g_flag[128];
__device__ int          g_aggv[128];
__device__ int          g_inclv[128];

// ---------------- K1: weighted in-degree + histogram + x->fp16 convert ------
__global__ void deg_conv_kernel(const float* __restrict__ x,
                                const int* __restrict__ ei,
                                const float* __restrict__ ew, int E, int n) {
    int i = blockIdx.x * blockDim.x + threadIdx.x;
    if (i < E) {
        int c = ei[E + i];
        atomicAdd(&g_deg[c], ew[i]);
        atomicAdd(&g_cnt[c], 1);
    }
    int q = n * 32;                               // float4 count
    int stride = gridDim.x * blockDim.x;
    for (int idx = i; idx < q; idx += stride) {
        float4 v = ((const float4*)x)[idx];
        __half2 h0 = __floats2half2_rn(v.x, v.y);
        __half2 h1 = __floats2half2_rn(v.z, v.w);
        uint2 u;
        u.x = *(unsigned int*)&h0;
        u.y = *(unsigned int*)&h1;
        ((uint2*)g_xh)[idx] = u;
    }
}

// ---------------- K2: dinv + single-pass exclusive scan (lookback) ----------
__global__ __launch_bounds__(SCAN_B) void scan_dinv_kernel(int n) {
    __shared__ int s[SCAN_B];
    __shared__ int s_pfx;
    int tid = threadIdx.x, b = blockIdx.x;
    int i = b * SCAN_B + tid;
    int v = (i < n) ? g_cnt[i] : 0;
    if (i < n) g_dinv[i] = rsqrtf(g_deg[i] + 1.0f);   // self-loop => deg>0
    s[tid] = v;
    __syncthreads();
    #pragma unroll
    for (int off = 1; off < SCAN_B; off <<= 1) {
        int t = (tid >= off) ? s[tid - off] : 0;
        __syncthreads();
        s[tid] += t;
        __syncthreads();
    }
    int incl  = s[tid];
    int total = s[SCAN_B - 1];
    if (tid == 0) {
        g_aggv[b] = total;
        __threadfence();
        g_flag[b] = 1;
        int pfx = 0;
        if (b > 0) {
            int j = b - 1;
            while (1) {
                int f;
                do { f = g_flag[j]; } while (f == 0);
                __threadfence();
                if (f == 2) { pfx += *((volatile int*)&g_inclv[j]); break; }
                pfx += *((volatile int*)&g_aggv[j]);
                j--;
                if (j < 0) break;
            }
        }
        g_inclv[b] = pfx + total;
        __threadfence();
        g_flag[b] = 2;
        s_pfx = pfx;
    }
    __syncthreads();
    if (i < n) {
        int st = s_pfx + incl - v;
        g_start[i]  = st;
        g_cursor[i] = st;
    }
}

// ---------------- K3: build CSR (by target) + reset scan flags --------------
__global__ void csr_kernel(const int* __restrict__ ei, const float* __restrict__ ew, int E) {
    if (blockIdx.x == 0 && threadIdx.x < 128) g_flag[threadIdx.x] = 0;  // restore invariant
    int e = blockIdx.x * blockDim.x + threadIdx.x;
    if (e >= E) return;
    int r = ei[e];
    int c = ei[E + e];
    float coef = g_dinv[r] * ew[e] * g_dinv[c];
    int pos = atomicAdd(&g_cursor[c], 1);
    g_csr[pos] = make_float2(__int_as_float(r), coef);
}

// ---------------- K4: shfl-batched pull gather (PROFILED SLOT) --------------
__device__ __forceinline__ void fma_edge(float4& acc, float coef, uint2 raw) {
    __half2 h0 = *(__half2*)&raw.x;
    __half2 h1 = *(__half2*)&raw.y;
    float2 f0 = __half22float2(h0);
    float2 f1 = __half22float2(h1);
    acc.x += coef * f0.x;  acc.y += coef * f0.y;
    acc.z += coef * f1.x;  acc.w += coef * f1.y;
}

__global__ __launch_bounds__(256) void gather_kernel(const float* __restrict__ x, int n) {
    int warp = (blockIdx.x * blockDim.x + threadIdx.x) >> 5;
    int lane = threadIdx.x & 31;
    if (warp >= n) return;

    const uint2* xh = (const uint2*)g_xh;
    int start = g_start[warp];
    int cnt   = g_cnt[warp];
    float d   = g_dinv[warp];
    if (lane == 0) { g_deg[warp] = 0.f; g_cnt[warp] = 0; }   // restore invariant

    float4 xv = ((const float4*)x)[(size_t)warp * 32 + lane];
    float d2 = d * d;
    float4 acc  = make_float4(d2 * xv.x, d2 * xv.y, d2 * xv.z, d2 * xv.w);
    float4 acc2 = make_float4(0.f, 0.f, 0.f, 0.f);

    const float2* cs = g_csr + start;
    for (int base = 0; base < cnt; base += 32) {
        int rem = cnt - base;
        int m = rem < 32 ? rem : 32;
        // one coalesced 256B load grabs up to 32 edge records for the warp
        float2 a = make_float2(0.f, 0.f);
        if (lane < m) a = cs[base + lane];
        int   rA = __float_as_int(a.x);
        float cA = a.y;

        int t = 0;
        for (; t + 3 < m; t += 4) {
            int   r0 = __shfl_sync(0xffffffffu, rA, t);
            float c0 = __shfl_sync(0xffffffffu, cA, t);
            int   r1 = __shfl_sync(0xffffffffu, rA, t + 1);
            float c1 = __shfl_sync(0xffffffffu, cA, t + 1);
            int   r2 = __shfl_sync(0xffffffffu, rA, t + 2);
            float c2 = __shfl_sync(0xffffffffu, cA, t + 2);
            int   r3 = __shfl_sync(0xffffffffu, rA, t + 3);
            float c3 = __shfl_sync(0xffffffffu, cA, t + 3);
            uint2 v0 = xh[(size_t)r0 * 32 + lane];
            uint2 v1 = xh[(size_t)r1 * 32 + lane];
            uint2 v2 = xh[(size_t)r2 * 32 + lane];
            uint2 v3 = xh[(size_t)r3 * 32 + lane];
            fma_edge(acc,  c0, v0);
            fma_edge(acc2, c1, v1);
            fma_edge(acc,  c2, v2);
            fma_edge(acc2, c3, v3);
        }
        for (; t < m; t++) {
            int   r0 = __shfl_sync(0xffffffffu, rA, t);
            float c0 = __shfl_sync(0xffffffffu, cA, t);
            uint2 v0 = xh[(size_t)r0 * 32 + lane];
            fma_edge(acc, c0, v0);
        }
    }
    acc.x += acc2.x; acc.y += acc2.y; acc.z += acc2.z; acc.w += acc2.w;
    // store agg as fp16 (halves store + later GEMM read traffic)
    __half2 h0 = __floats2half2_rn(acc.x, acc.y);
    __half2 h1 = __floats2half2_rn(acc.z, acc.w);
    uint2 u;
    u.x = *(unsigned int*)&h0;
    u.y = *(unsigned int*)&h1;
    ((uint2*)g_aggh)[(size_t)warp * 32 + lane] = u;
}

// ---------------- K5: agg @ W + b, relu, smem-staged segment-max pool -------
#define AS_LD 130
#define BK 64
__global__ __launch_bounds__(256, 2) void gemm_pool_kernel(
        const float* __restrict__ w,       // [128,128]
        const float* __restrict__ bias,    // [128]
        const int*   __restrict__ batch,
        int n) {
    extern __shared__ float sm[];
    float* As = sm;                   // 128*130
    float* Bs = sm + 128 * AS_LD;     // 64*128 (reused as smem pool in epilogue)

    int tid  = threadIdx.x;
    int row0 = blockIdx.x * 128;

    // load A tile from fp16 agg, convert to fp32 in smem
    {
        const uint2* agg2 = (const uint2*)g_aggh;
        #pragma unroll
        for (int i = tid; i < 4096; i += 256) {
            int rr = i >> 5, kq = i & 31;
            int gr = row0 + rr;
            float4 v = make_float4(0.f, 0.f, 0.f, 0.f);
            if (gr < n) {
                uint2 u = agg2[(size_t)gr * 32 + kq];
                __half2 h0 = *(__half2*)&u.x;
                __half2 h1 = *(__half2*)&u.y;
                float2 f0 = __half22float2(h0);
                float2 f1 = __half22float2(h1);
                v = make_float4(f0.x, f0.y, f1.x, f1.y);
            }
            float* p = As + rr * AS_LD + kq * 4;
            p[0] = v.x; p[1] = v.y; p[2] = v.z; p[3] = v.w;
        }
    }

    int ty = tid >> 4, tx = tid & 15;
    int r0 = ty * 8, c0 = tx * 8;
    float acc[8][8];
    #pragma unroll
    for (int i = 0; i < 8; i++)
        #pragma unroll
        for (int j = 0; j < 8; j++) acc[i][j] = 0.f;

    const float4* Bs4 = (const float4*)Bs;
    for (int chunk = 0; chunk < 2; chunk++) {
        __syncthreads();
        {
            const float4* w4 = (const float4*)(w + chunk * BK * 128);
            float4* b4 = (float4*)Bs;
            #pragma unroll
            for (int i = tid; i < 2048; i += 256) b4[i] = w4[i];
        }
        __syncthreads();
        int kbase = chunk * BK;
        #pragma unroll 4
        for (int k = 0; k < BK; k++) {
            float a[8];
            #pragma unroll
            for (int i = 0; i < 8; i++) a[i] = As[(r0 + i) * AS_LD + kbase + k];
            float4 b0 = Bs4[k * 32 + tx * 2];
            float4 b1 = Bs4[k * 32 + tx * 2 + 1];
            float b[8] = {b0.x, b0.y, b0.z, b0.w, b1.x, b1.y, b1.z, b1.w};
            #pragma unroll
            for (int i = 0; i < 8; i++)
                #pragma unroll
                for (int j = 0; j < 8; j++) acc[i][j] += a[i] * b[j];
        }
    }

    // ---- epilogue: bias + relu + segment-max, staged through smem ----
    __syncthreads();                               // done reading Bs
    unsigned int* sp = (unsigned int*)Bs;          // [4][128] local pool
    for (int i = tid; i < 512; i += 256) sp[i] = 0u;
    __syncthreads();

    int g_lo = batch[row0];
    float bb[8];
    #pragma unroll
    for (int j = 0; j < 8; j++) bb[j] = bias[c0 + j];

    int prevg = -1;
    float m[8];
    #pragma unroll
    for (int j = 0; j < 8; j++) m[j] = 0.f;

    #define EMIT_SEG(gseg)                                                     \
        do {                                                                   \
            int s_ = (gseg) - g_lo;                                            \
            if (s_ < 4) {                                                      \
                _Pragma("unroll")                                              \
                for (int j = 0; j < 8; j++)                                    \
                    atomicMax(&sp[s_ * 128 + c0 + j], __float_as_uint(m[j]));  \
            } else {                                                           \
                _Pragma("unroll")                                              \
                for (int j = 0; j < 8; j++)                                    \
                    atomicMax(&g_pool[(gseg) * F + c0 + j], __float_as_uint(m[j])); \
            }                                                                  \
        } while (0)

    for (int i = 0; i < 8; i++) {
        int gr = row0 + r0 + i;
        if (gr >= n) break;
        int g = batch[gr];
        if (g != prevg) {
            if (prevg >= 0) EMIT_SEG(prevg);
            prevg = g;
            #pragma unroll
            for (int j = 0; j < 8; j++) m[j] = fmaxf(acc[i][j] + bb[j], 0.f);
        } else {
            #pragma unroll
            for (int j = 0; j < 8; j++) m[j] = fmaxf(m[j], fmaxf(acc[i][j] + bb[j], 0.f));
        }
    }
    if (prevg >= 0) EMIT_SEG(prevg);
    __syncthreads();

    // flush local pool (skip zeros: relu >= 0 and global pool init is 0)
    for (int i = tid; i < 512; i += 256) {
        unsigned int v = sp[i];
        if (v) {
            int s = i >> 7, j = i & 127;
            atomicMax(&g_pool[(g_lo + s) * F + j], v);
        }
    }
}

// ---------------- K6: fused MLP head (one block) + pool reset ---------------
__global__ __launch_bounds__(1024) void head_kernel(
        const float* __restrict__ w1, const float* __restrict__ b1,
        const float* __restrict__ w2, const float* __restrict__ b2,
        float* __restrict__ out) {
    __shared__ float t1s[NUM_GRAPHS * LIN_H];   // 16KB
    int tid = threadIdx.x;
    for (int idx = tid; idx < NUM_GRAPHS * LIN_H; idx += 1024) {
        int g = idx >> 6, j = idx & 63;
        float s = b1[j];
        #pragma unroll 8
        for (int k = 0; k < F; k++)
            s += __uint_as_float(g_pool[g * F + k]) * w1[k * LIN_H + j];
        t1s[idx] = fmaxf(s, 0.f);
    }
    __syncthreads();
    for (int idx = tid; idx < NUM_GRAPHS * F; idx += 1024)   // restore invariant
        g_pool[idx] = 0u;
    for (int idx = tid; idx < NUM_GRAPHS * N_CLASSES; idx += 1024) {
        int g = idx / N_CLASSES, c = idx % N_CLASSES;
        float s = b2[c];
        #pragma unroll 8
        for (int j = 0; j < LIN_H; j++)
            s += t1s[g * LIN_H + j] * w2[j * N_CLASSES + c];
        out[idx] = s;
    }
}

// ---------------- launch ----------------------------------------------------
extern "C" void kernel_launch(void* const* d_in, const int* in_sizes, int n_in,
                              void* d_out, int out_size) {
    const float* x      = (const float*)d_in[0];
    const int*   ei     = (const int*)d_in[1];
    const float* ew     = (const float*)d_in[2];
    const int*   batch  = (const int*)d_in[3];
    const float* conv_w = (const float*)d_in[4];
    const float* conv_b = (const float*)d_in[5];
    const float* lin1_w = (const float*)d_in[6];
    const float* lin1_b = (const float*)d_in[7];
    const float* lin2_w = (const float*)d_in[8];
    const float* lin2_b = (const float*)d_in[9];
    float* out = (float*)d_out;

    int E = in_sizes[2];
    int n = in_sizes[3];
    int nscan = (n + SCAN_B - 1) / SCAN_B;

    const int smem_gemm = (128 * AS_LD + BK * 128) * (int)sizeof(float);
    cudaFuncSetAttribute(gemm_pool_kernel,
                         cudaFuncAttributeMaxDynamicSharedMemorySize, smem_gemm);

    deg_conv_kernel<<<(E + 255) / 256, 256>>>(x, ei, ew, E, n);
    scan_dinv_kernel<<<nscan, SCAN_B>>>(n);
    csr_kernel<<<(E + 255) / 256, 256>>>(ei, ew, E);
    gather_kernel<<<(n + 7) / 8, 256>>>(x, n);                  // profiled slot #4
    gemm_pool_kernel<<<(n + 127) / 128, 256, smem_gemm>>>(conv_w, conv_b, batch, n);
    head_kernel<<<1, 1024>>>(lin1_w, lin1_b, lin2_w, lin2_b, out);
}

// round 10
// speedup vs baseline: 1.3438x; 1.3438x over previous
#include <cuda_runtime.h>
#include <cuda_fp16.h>
#include <mma.h>
#include <cstdint>

using namespace nvcuda;

// Problem constants (shapes fixed by the dataset)
#define N_NODES_MAX 100096
#define E_MAX       1600000
#define F 128
#define LIN_H 64
#define N_CLASSES 10
#define NUM_GRAPHS 64
#define SCAN_B 1024

// ---------------- scratch (device globals; zero-initialized at load) --------
// Invariant: every kernel_launch call leaves g_deg/g_cnt/g_flag/g_pool zeroed
// again (self-restoring), so graph replays are deterministic.
__device__ float        g_deg[N_NODES_MAX];
__device__ int          g_cnt[N_NODES_MAX];
__device__ int          g_start[N_NODES_MAX];
__device__ int          g_cursor[N_NODES_MAX];
__device__ float        g_dinv[N_NODES_MAX];
__device__ float2       g_csr[E_MAX];                         // (src as int bits, coef)
__device__ __half       g_xh[(size_t)N_NODES_MAX * F];        // 25.6 MB fp16 copy of x
__device__ __half       g_aggh[(size_t)N_NODES_MAX * F];      // 25.6 MB fp16 agg
__device__ unsigned int g_pool[NUM_GRAPHS * F];               // float-as-uint max
// decoupled-lookback scan state
__device__ volatile int g_flag[128];
__device__ int          g_aggv[128];
__device__ int          g_inclv[128];

// ---------------- K1: weighted in-degree + histogram + x->fp16 convert ------
__global__ void deg_conv_kernel(const float* __restrict__ x,
                                const int* __restrict__ ei,
                                const float* __restrict__ ew, int E, int n) {
    int i = blockIdx.x * blockDim.x + threadIdx.x;
    if (i < E) {
        int c = ei[E + i];
        atomicAdd(&g_deg[c], ew[i]);
        atomicAdd(&g_cnt[c], 1);
    }
    int q = n * 32;                               // float4 count
    int stride = gridDim.x * blockDim.x;
    for (int idx = i; idx < q; idx += stride) {
        float4 v = ((const float4*)x)[idx];
        __half2 h0 = __floats2half2_rn(v.x, v.y);
        __half2 h1 = __floats2half2_rn(v.z, v.w);
        uint2 u;
        u.x = *(unsigned int*)&h0;
        u.y = *(unsigned int*)&h1;
        ((uint2*)g_xh)[idx] = u;
    }
}

// ---------------- K2: dinv + single-pass exclusive scan (lookback) ----------
__global__ __launch_bounds__(SCAN_B) void scan_dinv_kernel(int n) {
    __shared__ int s[SCAN_B];
    __shared__ int s_pfx;
    int tid = threadIdx.x, b = blockIdx.x;
    int i = b * SCAN_B + tid;
    int v = (i < n) ? g_cnt[i] : 0;
    if (i < n) g_dinv[i] = rsqrtf(g_deg[i] + 1.0f);   // self-loop => deg>0
    s[tid] = v;
    __syncthreads();
    #pragma unroll
    for (int off = 1; off < SCAN_B; off <<= 1) {
        int t = (tid >= off) ? s[tid - off] : 0;
        __syncthreads();
        s[tid] += t;
        __syncthreads();
    }
    int incl  = s[tid];
    int total = s[SCAN_B - 1];
    if (tid == 0) {
        g_aggv[b] = total;
        __threadfence();
        g_flag[b] = 1;
        int pfx = 0;
        if (b > 0) {
            int j = b - 1;
            while (1) {
                int f;
                do { f = g_flag[j]; } while (f == 0);
                __threadfence();
                if (f == 2) { pfx += *((volatile int*)&g_inclv[j]); break; }
                pfx += *((volatile int*)&g_aggv[j]);
                j--;
                if (j < 0) break;
            }
        }
        g_inclv[b] = pfx + total;
        __threadfence();
        g_flag[b] = 2;
        s_pfx = pfx;
    }
    __syncthreads();
    if (i < n) {
        int st = s_pfx + incl - v;
        g_start[i]  = st;
        g_cursor[i] = st;
    }
}

// ---------------- K3: build CSR (by target) + reset scan flags --------------
__global__ void csr_kernel(const int* __restrict__ ei, const float* __restrict__ ew, int E) {
    if (blockIdx.x == 0 && threadIdx.x < 128) g_flag[threadIdx.x] = 0;  // restore invariant
    int e = blockIdx.x * blockDim.x + threadIdx.x;
    if (e >= E) return;
    int r = ei[e];
    int c = ei[E + e];
    float coef = g_dinv[r] * ew[e] * g_dinv[c];
    int pos = atomicAdd(&g_cursor[c], 1);
    g_csr[pos] = make_float2(__int_as_float(r), coef);
}

// ---------------- K4: pull gather (R7 loop restored; PROFILED SLOT) ---------
__device__ __forceinline__ void fma_edge(float4& acc, float coef, uint2 raw) {
    __half2 h0 = *(__half2*)&raw.x;
    __half2 h1 = *(__half2*)&raw.y;
    float2 f0 = __half22float2(h0);
    float2 f1 = __half22float2(h1);
    acc.x += coef * f0.x;  acc.y += coef * f0.y;
    acc.z += coef * f1.x;  acc.w += coef * f1.y;
}

__global__ __launch_bounds__(256) void gather_kernel(const float* __restrict__ x, int n) {
    int warp = (blockIdx.x * blockDim.x + threadIdx.x) >> 5;
    int lane = threadIdx.x & 31;
    if (warp >= n) return;

    const uint2* xh = (const uint2*)g_xh;
    int start = g_start[warp];
    int cnt   = g_cnt[warp];
    float d   = g_dinv[warp];
    if (lane == 0) { g_deg[warp] = 0.f; g_cnt[warp] = 0; }   // restore invariant

    float4 xv = ((const float4*)x)[(size_t)warp * 32 + lane];
    float d2 = d * d;
    float4 acc  = make_float4(d2 * xv.x, d2 * xv.y, d2 * xv.z, d2 * xv.w);
    float4 acc2 = make_float4(0.f, 0.f, 0.f, 0.f);

    const float2* cs = g_csr + start;
    int e = 0;
    for (; e + 3 < cnt; e += 4) {
        float2 a0 = cs[e];
        float2 a1 = cs[e + 1];
        float2 a2 = cs[e + 2];
        float2 a3 = cs[e + 3];
        uint2 v0 = xh[(size_t)__float_as_int(a0.x) * 32 + lane];
        uint2 v1 = xh[(size_t)__float_as_int(a1.x) * 32 + lane];
        uint2 v2 = xh[(size_t)__float_as_int(a2.x) * 32 + lane];
        uint2 v3 = xh[(size_t)__float_as_int(a3.x) * 32 + lane];
        fma_edge(acc,  a0.y, v0);
        fma_edge(acc2, a1.y, v1);
        fma_edge(acc,  a2.y, v2);
        fma_edge(acc2, a3.y, v3);
    }
    for (; e < cnt; e++) {
        float2 a0 = cs[e];
        uint2 v0 = xh[(size_t)__float_as_int(a0.x) * 32 + lane];
        fma_edge(acc, a0.y, v0);
    }
    acc.x += acc2.x; acc.y += acc2.y; acc.z += acc2.z; acc.w += acc2.w;
    // store agg as fp16 (halves store + tensor-core GEMM A operand)
    __half2 h0 = __floats2half2_rn(acc.x, acc.y);
    __half2 h1 = __floats2half2_rn(acc.z, acc.w);
    uint2 u;
    u.x = *(unsigned int*)&h0;
    u.y = *(unsigned int*)&h1;
    ((uint2*)g_aggh)[(size_t)warp * 32 + lane] = u;
}

// ---------------- K5: tensor-core GEMM + bias/relu/segment-max pool ---------
// 128 rows x 128 cols per block, 8 warps. A (fp16) and W (fp32->fp16) staged
// in smem; wmma m16n16k16 fp16*fp16 -> fp32; C overlaid on A/W smem; fused
// epilogue with smem-staged pooling.
#define A_LDH 136                     // halves per row (pad 16B)
#define C_LDF 132                     // floats per row (pad 16B)
__global__ __launch_bounds__(256, 2) void gemm_pool_tc_kernel(
        const float* __restrict__ w,       // [128,128] fp32
        const float* __restrict__ bias,    // [128]
        const int*   __restrict__ batch,
        int n) {
    extern __shared__ char smraw[];
    __half* Ah = (__half*)smraw;                 // 128*136 halves = 34816B
    __half* Wh = Ah + 128 * A_LDH;               // 128*136 halves = 34816B
    float*  Cs = (float*)smraw;                  // overlay: 128*132 floats = 67584B
    __shared__ unsigned int sp[4 * 128];         // block-local pool

    int tid = threadIdx.x;
    int wid = tid >> 5;
    int lane = tid & 31;
    int row0 = blockIdx.x * 128;

    for (int i = tid; i < 512; i += 256) sp[i] = 0u;

    // stage A rows (fp16, 16 uint4 per row)
    {
        const uint4* a4 = (const uint4*)g_aggh;          // 16 uint4 per row
        #pragma unroll
        for (int i = tid; i < 2048; i += 256) {
            int rr = i >> 4, kq = i & 15;
            int gr = row0 + rr;
            uint4 v = make_uint4(0u, 0u, 0u, 0u);
            if (gr < n) v = a4[(size_t)gr * 16 + kq];
            *(uint4*)((char*)(Ah + rr * A_LDH) + kq * 16) = v;
        }
    }
    // stage W, converting fp32 -> fp16 (128x128)
    {
        const float4* w4 = (const float4*)w;
        #pragma unroll
        for (int i = tid; i < 4096; i += 256) {
            int k = i >> 5, q = i & 31;                  // row k, 4-col group q
            float4 v = w4[i];
            __half2 h0 = __floats2half2_rn(v.x, v.y);
            __half2 h1 = __floats2half2_rn(v.z, v.w);
            uint2 u;
            u.x = *(unsigned int*)&h0;
            u.y = *(unsigned int*)&h1;
            *(uint2*)((char*)(Wh + k * A_LDH) + q * 8) = u;
        }
    }
    __syncthreads();

    // wmma: each warp computes a 16x128 strip (8 n-tiles), k-loop of 8
    wmma::fragment<wmma::accumulator, 16, 16, 16, float> c[8];
    #pragma unroll
    for (int nt = 0; nt < 8; nt++) wmma::fill_fragment(c[nt], 0.f);

    int r0 = wid * 16;
    #pragma unroll
    for (int k = 0; k < 8; k++) {
        wmma::fragment<wmma::matrix_a, 16, 16, 16, __half, wmma::row_major> a;
        wmma::load_matrix_sync(a, Ah + r0 * A_LDH + k * 16, A_LDH);
        #pragma unroll
        for (int nt = 0; nt < 8; nt++) {
            wmma::fragment<wmma::matrix_b, 16, 16, 16, __half, wmma::row_major> b;
            wmma::load_matrix_sync(b, Wh + (k * 16) * A_LDH + nt * 16, A_LDH);
            wmma::mma_sync(c[nt], a, b, c[nt]);
        }
    }
    __syncthreads();          // all warps done reading Ah/Wh before C overlay

    #pragma unroll
    for (int nt = 0; nt < 8; nt++)
        wmma::store_matrix_sync(Cs + r0 * C_LDF + nt * 16, c[nt], C_LDF,
                                wmma::mem_row_major);
    __syncwarp();             // warp reads back only its own strip

    // epilogue: bias + relu + segment-max over this warp's 16 rows
    int c0 = lane * 4;
    float bb[4];
    #pragma unroll
    for (int j = 0; j < 4; j++) bb[j] = bias[c0 + j];

    int g_lo = batch[row0];
    int prevg = -1;
    float m[4];
    #pragma unroll
    for (int j = 0; j < 4; j++) m[j] = 0.f;

    #define EMIT_SEG4(gseg)                                                    \
        do {                                                                   \
            int s_ = (gseg) - g_lo;                                            \
            if (s_ < 4) {                                                      \
                _Pragma("unroll")                                              \
                for (int j = 0; j < 4; j++)                                    \
                    atomicMax(&sp[s_ * 128 + c0 + j], __float_as_uint(m[j]));  \
            } else {                                                           \
                _Pragma("unroll")                                              \
                for (int j = 0; j < 4; j++)                                    \
                    atomicMax(&g_pool[(gseg) * F + c0 + j], __float_as_uint(m[j])); \
            }                                                                  \
        } while (0)

    for (int i = 0; i < 16; i++) {
        int gr = row0 + r0 + i;
        if (gr >= n) break;
        int g = batch[gr];
        float v[4];
        #pragma unroll
        for (int j = 0; j < 4; j++)
            v[j] = fmaxf(Cs[(r0 + i) * C_LDF + c0 + j] + bb[j], 0.f);
        if (g != prevg) {
            if (prevg >= 0) EMIT_SEG4(prevg);
            prevg = g;
            #pragma unroll
            for (int j = 0; j < 4; j++) m[j] = v[j];
        } else {
            #pragma unroll
            for (int j = 0; j < 4; j++) m[j] = fmaxf(m[j], v[j]);
        }
    }
    if (prevg >= 0) EMIT_SEG4(prevg);
    __syncthreads();

    // flush local pool (skip zeros: relu >= 0 and global pool init is 0)
    for (int i = tid; i < 512; i += 256) {
        unsigned int v = sp[i];
        if (v) {
            int s = i >> 7, j = i & 127;
            atomicMax(&g_pool[(g_lo + s) * F + j], v);
        }
    }
}

// ---------------- K6: fused MLP head (one block) + pool reset ---------------
__global__ __launch_bounds__(1024) void head_kernel(
        const float* __restrict__ w1, const float* __restrict__ b1,
        const float* __restrict__ w2, const float* __restrict__ b2,
        float* __restrict__ out) {
    __shared__ float t1s[NUM_GRAPHS * LIN_H];   // 16KB
    int tid = threadIdx.x;
    for (int idx = tid; idx < NUM_GRAPHS * LIN_H; idx += 1024) {
        int g = idx >> 6, j = idx & 63;
        float s = b1[j];
        #pragma unroll 8
        for (int k = 0; k < F; k++)
            s += __uint_as_float(g_pool[g * F + k]) * w1[k * LIN_H + j];
        t1s[idx] = fmaxf(s, 0.f);
    }
    __syncthreads();
    for (int idx = tid; idx < NUM_GRAPHS * F; idx += 1024)   // restore invariant
        g_pool[idx] = 0u;
    for (int idx = tid; idx < NUM_GRAPHS * N_CLASSES; idx += 1024) {
        int g = idx / N_CLASSES, c = idx % N_CLASSES;
        float s = b2[c];
        #pragma unroll 8
        for (int j = 0; j < LIN_H; j++)
            s += t1s[g * LIN_H + j] * w2[j * N_CLASSES + c];
        out[idx] = s;
    }
}

// ---------------- launch ----------------------------------------------------
extern "C" void kernel_launch(void* const* d_in, const int* in_sizes, int n_in,
                              void* d_out, int out_size) {
    const float* x      = (const float*)d_in[0];
    const int*   ei     = (const int*)d_in[1];
    const float* ew     = (const float*)d_in[2];
    const int*   batch  = (const int*)d_in[3];
    const float* conv_w = (const float*)d_in[4];
    const float* conv_b = (const float*)d_in[5];
    const float* lin1_w = (const float*)d_in[6];
    const float* lin1_b = (const float*)d_in[7];
    const float* lin2_w = (const float*)d_in[8];
    const float* lin2_b = (const float*)d_in[9];
    float* out = (float*)d_out;

    int E = in_sizes[2];
    int n = in_sizes[3];
    int nscan = (n + SCAN_B - 1) / SCAN_B;

    const int smem_gemm = 2 * 128 * A_LDH * (int)sizeof(__half);   // 69632B
    cudaFuncSetAttribute(gemm_pool_tc_kernel,
                         cudaFuncAttributeMaxDynamicSharedMemorySize, smem_gemm);

    deg_conv_kernel<<<(E + 255) / 256, 256>>>(x, ei, ew, E, n);
    scan_dinv_kernel<<<nscan, SCAN_B>>>(n);
    csr_kernel<<<(E + 255) / 256, 256>>>(ei, ew, E);
    gather_kernel<<<(n + 7) / 8, 256>>>(x, n);                  // profiled slot #4
    gemm_pool_tc_kernel<<<(n + 127) / 128, 256, smem_gemm>>>(conv_w, conv_b, batch, n);
    head_kernel<<<1, 1024>>>(lin1_w, lin1_b, lin2_w, lin2_b, out);
}

// round 11
// speedup vs baseline: 1.4330x; 1.0664x over previous
#include <cuda_runtime.h>
#include <cuda_fp16.h>
#include <mma.h>
#include <cstdint>

using namespace nvcuda;

// Problem constants (shapes fixed by the dataset)
#define N_NODES_MAX 100096
#define E_MAX       1600000
#define F 128
#define LIN_H 64
#define N_CLASSES 10
#define NUM_GRAPHS 64
#define SCAN_B 1024

// ---------------- scratch (device globals; zero-initialized at load) --------
// Invariant: every kernel_launch call leaves g_deg/g_cnt/g_flag/g_pool zeroed
// again (self-restoring), so graph replays are deterministic.
__device__ float        g_deg[N_NODES_MAX];
__device__ int          g_cnt[N_NODES_MAX];
__device__ int          g_start[N_NODES_MAX];
__device__ int          g_cursor[N_NODES_MAX];
__device__ float        g_dinv[N_NODES_MAX];
__device__ float2       g_csr[E_MAX];                         // (src as int bits, coef)
__device__ __half       g_xh[(size_t)N_NODES_MAX * F];        // 25.6 MB fp16 copy of x
__device__ __half       g_aggh[(size_t)N_NODES_MAX * F];      // 25.6 MB fp16 agg
__device__ unsigned int g_pool[NUM_GRAPHS * F];               // float-as-uint max
// decoupled-lookback scan state
__device__ volatile int g_flag[128];
__device__ int          g_aggv[128];
__device__ int          g_inclv[128];

// ---------------- K1: weighted in-degree + histogram + x->fp16 convert ------
__global__ void deg_conv_kernel(const float* __restrict__ x,
                                const int* __restrict__ ei,
                                const float* __restrict__ ew, int E, int n) {
    int i = blockIdx.x * blockDim.x + threadIdx.x;
    if (i < E) {
        int c = ei[E + i];
        atomicAdd(&g_deg[c], ew[i]);
        atomicAdd(&g_cnt[c], 1);
    }
    int q = n * 32;                               // float4 count
    int stride = gridDim.x * blockDim.x;
    for (int idx = i; idx < q; idx += stride) {
        float4 v = ((const float4*)x)[idx];
        __half2 h0 = __floats2half2_rn(v.x, v.y);
        __half2 h1 = __floats2half2_rn(v.z, v.w);
        uint2 u;
        u.x = *(unsigned int*)&h0;
        u.y = *(unsigned int*)&h1;
        ((uint2*)g_xh)[idx] = u;
    }
}

// ---------------- K2: dinv + single-pass exclusive scan (lookback) ----------
__global__ __launch_bounds__(SCAN_B) void scan_dinv_kernel(int n) {
    __shared__ int s[SCAN_B];
    __shared__ int s_pfx;
    int tid = threadIdx.x, b = blockIdx.x;
    int i = b * SCAN_B + tid;
    int v = (i < n) ? g_cnt[i] : 0;
    if (i < n) g_dinv[i] = rsqrtf(g_deg[i] + 1.0f);   // self-loop => deg>0
    s[tid] = v;
    __syncthreads();
    #pragma unroll
    for (int off = 1; off < SCAN_B; off <<= 1) {
        int t = (tid >= off) ? s[tid - off] : 0;
        __syncthreads();
        s[tid] += t;
        __syncthreads();
    }
    int incl  = s[tid];
    int total = s[SCAN_B - 1];
    if (tid == 0) {
        g_aggv[b] = total;
        __threadfence();
        g_flag[b] = 1;
        int pfx = 0;
        if (b > 0) {
            int j = b - 1;
            while (1) {
                int f;
                do { f = g_flag[j]; } while (f == 0);
                __threadfence();
                if (f == 2) { pfx += *((volatile int*)&g_inclv[j]); break; }
                pfx += *((volatile int*)&g_aggv[j]);
                j--;
                if (j < 0) break;
            }
        }
        g_inclv[b] = pfx + total;
        __threadfence();
        g_flag[b] = 2;
        s_pfx = pfx;
    }
    __syncthreads();
    if (i < n) {
        int st = s_pfx + incl - v;
        g_start[i]  = st;
        g_cursor[i] = st;
    }
}

// ---------------- K3: build CSR (by target) + reset scan flags --------------
__global__ void csr_kernel(const int* __restrict__ ei, const float* __restrict__ ew, int E) {
    if (blockIdx.x == 0 && threadIdx.x < 128) g_flag[threadIdx.x] = 0;  // restore invariant
    int e = blockIdx.x * blockDim.x + threadIdx.x;
    if (e >= E) return;
    int r = ei[e];
    int c = ei[E + e];
    float coef = g_dinv[r] * ew[e] * g_dinv[c];
    int pos = atomicAdd(&g_cursor[c], 1);
    g_csr[pos] = make_float2(__int_as_float(r), coef);
}

// ---------------- K4: pull gather, HALF-WARP per node (PROFILED SLOT) -------
// 16 lanes cover a 256B fp16 row (one uint4 each). Two nodes per warp =>
// 8 independent gather chains per warp at 4-way unroll.
__device__ __forceinline__ void fma_edge8(float4& a, float4& b, float coef, uint4 raw) {
    __half2 h0 = *(__half2*)&raw.x;
    __half2 h1 = *(__half2*)&raw.y;
    __half2 h2 = *(__half2*)&raw.z;
    __half2 h3 = *(__half2*)&raw.w;
    float2 f0 = __half22float2(h0);
    float2 f1 = __half22float2(h1);
    float2 f2 = __half22float2(h2);
    float2 f3 = __half22float2(h3);
    a.x += coef * f0.x;  a.y += coef * f0.y;
    a.z += coef * f1.x;  a.w += coef * f1.y;
    b.x += coef * f2.x;  b.y += coef * f2.y;
    b.z += coef * f3.x;  b.w += coef * f3.y;
}

__global__ __launch_bounds__(256) void gather_kernel(const float* __restrict__ x, int n) {
    int node = (blockIdx.x * blockDim.x + threadIdx.x) >> 4;
    int lane = threadIdx.x & 15;
    if (node >= n) return;

    const uint4* xh4 = (const uint4*)g_xh;    // 16 uint4 per row
    int start = g_start[node];
    int cnt   = g_cnt[node];
    float d   = g_dinv[node];
    if (lane == 0) { g_deg[node] = 0.f; g_cnt[node] = 0; }   // restore invariant

    // self-loop init: 8 fp32 features per lane
    const float4* x4 = (const float4*)x;      // 32 float4 per row
    float4 xa = x4[(size_t)node * 32 + lane * 2];
    float4 xb = x4[(size_t)node * 32 + lane * 2 + 1];
    float d2 = d * d;
    float4 accA  = make_float4(d2 * xa.x, d2 * xa.y, d2 * xa.z, d2 * xa.w);
    float4 accB  = make_float4(d2 * xb.x, d2 * xb.y, d2 * xb.z, d2 * xb.w);
    float4 accA2 = make_float4(0.f, 0.f, 0.f, 0.f);
    float4 accB2 = make_float4(0.f, 0.f, 0.f, 0.f);

    const float2* cs = g_csr + start;
    int e = 0;
    for (; e + 3 < cnt; e += 4) {
        float2 a0 = cs[e];
        float2 a1 = cs[e + 1];
        float2 a2 = cs[e + 2];
        float2 a3 = cs[e + 3];
        uint4 v0 = xh4[(size_t)__float_as_int(a0.x) * 16 + lane];
        uint4 v1 = xh4[(size_t)__float_as_int(a1.x) * 16 + lane];
        uint4 v2 = xh4[(size_t)__float_as_int(a2.x) * 16 + lane];
        uint4 v3 = xh4[(size_t)__float_as_int(a3.x) * 16 + lane];
        fma_edge8(accA,  accB,  a0.y, v0);
        fma_edge8(accA2, accB2, a1.y, v1);
        fma_edge8(accA,  accB,  a2.y, v2);
        fma_edge8(accA2, accB2, a3.y, v3);
    }
    for (; e < cnt; e++) {
        float2 a0 = cs[e];
        uint4 v0 = xh4[(size_t)__float_as_int(a0.x) * 16 + lane];
        fma_edge8(accA, accB, a0.y, v0);
    }
    accA.x += accA2.x; accA.y += accA2.y; accA.z += accA2.z; accA.w += accA2.w;
    accB.x += accB2.x; accB.y += accB2.y; accB.z += accB2.z; accB.w += accB2.w;

    // store agg as fp16: one uint4 (8 halves) per lane
    __half2 h0 = __floats2half2_rn(accA.x, accA.y);
    __half2 h1 = __floats2half2_rn(accA.z, accA.w);
    __half2 h2 = __floats2half2_rn(accB.x, accB.y);
    __half2 h3 = __floats2half2_rn(accB.z, accB.w);
    uint4 u;
    u.x = *(unsigned int*)&h0;
    u.y = *(unsigned int*)&h1;
    u.z = *(unsigned int*)&h2;
    u.w = *(unsigned int*)&h3;
    ((uint4*)g_aggh)[(size_t)node * 16 + lane] = u;
}

// ---------------- K5: tensor-core GEMM + bias/relu/segment-max pool ---------
#define A_LDH 136                     // halves per row (pad 16B)
#define C_LDF 132                     // floats per row (pad 16B)
__global__ __launch_bounds__(256, 2) void gemm_pool_tc_kernel(
        const float* __restrict__ w,       // [128,128] fp32
        const float* __restrict__ bias,    // [128]
        const int*   __restrict__ batch,
        int n) {
    extern __shared__ char smraw[];
    __half* Ah = (__half*)smraw;                 // 128*136 halves
    __half* Wh = Ah + 128 * A_LDH;               // 128*136 halves
    float*  Cs = (float*)smraw;                  // overlay: 128*132 floats
    __shared__ unsigned int sp[4 * 128];         // block-local pool

    int tid = threadIdx.x;
    int wid = tid >> 5;
    int lane = tid & 31;
    int row0 = blockIdx.x * 128;

    for (int i = tid; i < 512; i += 256) sp[i] = 0u;

    // stage A rows (fp16, 16 uint4 per row)
    {
        const uint4* a4 = (const uint4*)g_aggh;
        #pragma unroll
        for (int i = tid; i < 2048; i += 256) {
            int rr = i >> 4, kq = i & 15;
            int gr = row0 + rr;
            uint4 v = make_uint4(0u, 0u, 0u, 0u);
            if (gr < n) v = a4[(size_t)gr * 16 + kq];
            *(uint4*)((char*)(Ah + rr * A_LDH) + kq * 16) = v;
        }
    }
    // stage W, converting fp32 -> fp16 (128x128)
    {
        const float4* w4 = (const float4*)w;
        #pragma unroll
        for (int i = tid; i < 4096; i += 256) {
            int k = i >> 5, q = i & 31;
            float4 v = w4[i];
            __half2 h0 = __floats2half2_rn(v.x, v.y);
            __half2 h1 = __floats2half2_rn(v.z, v.w);
            uint2 u;
            u.x = *(unsigned int*)&h0;
            u.y = *(unsigned int*)&h1;
            *(uint2*)((char*)(Wh + k * A_LDH) + q * 8) = u;
        }
    }
    __syncthreads();

    // wmma: each warp computes a 16x128 strip (8 n-tiles), k-loop of 8
    wmma::fragment<wmma::accumulator, 16, 16, 16, float> c[8];
    #pragma unroll
    for (int nt = 0; nt < 8; nt++) wmma::fill_fragment(c[nt], 0.f);

    int r0 = wid * 16;
    #pragma unroll
    for (int k = 0; k < 8; k++) {
        wmma::fragment<wmma::matrix_a, 16, 16, 16, __half, wmma::row_major> a;
        wmma::load_matrix_sync(a, Ah + r0 * A_LDH + k * 16, A_LDH);
        #pragma unroll
        for (int nt = 0; nt < 8; nt++) {
            wmma::fragment<wmma::matrix_b, 16, 16, 16, __half, wmma::row_major> b;
            wmma::load_matrix_sync(b, Wh + (k * 16) * A_LDH + nt * 16, A_LDH);
            wmma::mma_sync(c[nt], a, b, c[nt]);
        }
    }
    __syncthreads();          // all warps done reading Ah/Wh before C overlay

    #pragma unroll
    for (int nt = 0; nt < 8; nt++)
        wmma::store_matrix_sync(Cs + r0 * C_LDF + nt * 16, c[nt], C_LDF,
                                wmma::mem_row_major);
    __syncwarp();             // warp reads back only its own strip

    // epilogue: bias + relu + segment-max over this warp's 16 rows
    int c0 = lane * 4;
    float bb[4];
    #pragma unroll
    for (int j = 0; j < 4; j++) bb[j] = bias[c0 + j];

    int g_lo = batch[row0];
    int prevg = -1;
    float m[4];
    #pragma unroll
    for (int j = 0; j < 4; j++) m[j] = 0.f;

    #define EMIT_SEG4(gseg)                                                    \
        do {                                                                   \
            int s_ = (gseg) - g_lo;                                            \
            if (s_ < 4) {                                                      \
                _Pragma("unroll")                                              \
                for (int j = 0; j < 4; j++)                                    \
                    atomicMax(&sp[s_ * 128 + c0 + j], __float_as_uint(m[j]));  \
            } else {                                                           \
                _Pragma("unroll")                                              \
                for (int j = 0; j < 4; j++)                                    \
                    atomicMax(&g_pool[(gseg) * F + c0 + j], __float_as_uint(m[j])); \
            }                                                                  \
        } while (0)

    for (int i = 0; i < 16; i++) {
        int gr = row0 + r0 + i;
        if (gr >= n) break;
        int g = batch[gr];
        float v[4];
        #pragma unroll
        for (int j = 0; j < 4; j++)
            v[j] = fmaxf(Cs[(r0 + i) * C_LDF + c0 + j] + bb[j], 0.f);
        if (g != prevg) {
            if (prevg >= 0) EMIT_SEG4(prevg);
            prevg = g;
            #pragma unroll
            for (int j = 0; j < 4; j++) m[j] = v[j];
        } else {
            #pragma unroll
            for (int j = 0; j < 4; j++) m[j] = fmaxf(m[j], v[j]);
        }
    }
    if (prevg >= 0) EMIT_SEG4(prevg);
    __syncthreads();

    // flush local pool (skip zeros: relu >= 0 and global pool init is 0)
    for (int i = tid; i < 512; i += 256) {
        unsigned int v = sp[i];
        if (v) {
            int s = i >> 7, j = i & 127;
            atomicMax(&g_pool[(g_lo + s) * F + j], v);
        }
    }
}

// ---------------- K6: fused MLP head (one block) + pool reset ---------------
__global__ __launch_bounds__(1024) void head_kernel(
        const float* __restrict__ w1, const float* __restrict__ b1,
        const float* __restrict__ w2, const float* __restrict__ b2,
        float* __restrict__ out) {
    __shared__ float t1s[NUM_GRAPHS * LIN_H];   // 16KB
    int tid = threadIdx.x;
    for (int idx = tid; idx < NUM_GRAPHS * LIN_H; idx += 1024) {
        int g = idx >> 6, j = idx & 63;
        float s = b1[j];
        #pragma unroll 8
        for (int k = 0; k < F; k++)
            s += __uint_as_float(g_pool[g * F + k]) * w1[k * LIN_H + j];
        t1s[idx] = fmaxf(s, 0.f);
    }
    __syncthreads();
    for (int idx = tid; idx < NUM_GRAPHS * F; idx += 1024)   // restore invariant
        g_pool[idx] = 0u;
    for (int idx = tid; idx < NUM_GRAPHS * N_CLASSES; idx += 1024) {
        int g = idx / N_CLASSES, c = idx % N_CLASSES;
        float s = b2[c];
        #pragma unroll 8
        for (int j = 0; j < LIN_H; j++)
            s += t1s[g * LIN_H + j] * w2[j * N_CLASSES + c];
        out[idx] = s;
    }
}

// ---------------- launch ----------------------------------------------------
extern "C" void kernel_launch(void* const* d_in, const int* in_sizes, int n_in,
                              void* d_out, int out_size) {
    const float* x      = (const float*)d_in[0];
    const int*   ei     = (const int*)d_in[1];
    const float* ew     = (const float*)d_in[2];
    const int*   batch  = (const int*)d_in[3];
    const float* conv_w = (const float*)d_in[4];
    const float* conv_b = (const float*)d_in[5];
    const float* lin1_w = (const float*)d_in[6];
    const float* lin1_b = (const float*)d_in[7];
    const float* lin2_w = (const float*)d_in[8];
    const float* lin2_b = (const float*)d_in[9];
    float* out = (float*)d_out;

    int E = in_sizes[2];
    int n = in_sizes[3];
    int nscan = (n + SCAN_B - 1) / SCAN_B;

    const int smem_gemm = 2 * 128 * A_LDH * (int)sizeof(__half);   // 69632B
    cudaFuncSetAttribute(gemm_pool_tc_kernel,
                         cudaFuncAttributeMaxDynamicSharedMemorySize, smem_gemm);

    deg_conv_kernel<<<(E + 255) / 256, 256>>>(x, ei, ew, E, n);
    scan_dinv_kernel<<<nscan, SCAN_B>>>(n);
    csr_kernel<<<(E + 255) / 256, 256>>>(ei, ew, E);
    gather_kernel<<<(n + 15) / 16, 256>>>(x, n);                // profiled slot #4
    gemm_pool_tc_kernel<<<(n + 127) / 128, 256, smem_gemm>>>(conv_w, conv_b, batch, n);
    head_kernel<<<1, 1024>>>(lin1_w, lin1_b, lin2_w, lin2_b, out);
}

// round 12
// speedup vs baseline: 1.5547x; 1.0850x over previous
#include <cuda_runtime.h>
#include <cuda_fp16.h>
#include <mma.h>
#include <cstdint>

using namespace nvcuda;

// Problem constants (shapes fixed by the dataset)
#define N_NODES_MAX 100096
#define E_MAX       1600000
#define F 128
#define LIN_H 64
#define N_CLASSES 10
#define NUM_GRAPHS 64
#define SCAN_B 1024

// ---------------- scratch (device globals; zero-initialized at load) --------
// Invariant: every kernel_launch call leaves g_deg/g_cnt/g_flag/g_pool zeroed
// again (self-restoring), so graph replays are deterministic.
__device__ float        g_deg[N_NODES_MAX];
__device__ int          g_cnt[N_NODES_MAX];
__device__ int          g_start[N_NODES_MAX];
__device__ int          g_cursor[N_NODES_MAX];
__device__ float        g_dinv[N_NODES_MAX];
__device__ float2       g_csr[E_MAX];                         // (src as int bits, coef)
__device__ __half       g_xh[(size_t)N_NODES_MAX * F];        // 25.6 MB fp16 copy of x
__device__ __half       g_aggh[(size_t)N_NODES_MAX * F];      // 25.6 MB fp16 agg
__device__ unsigned int g_pool[NUM_GRAPHS * F];               // float-as-uint max
// decoupled-lookback scan state
__device__ volatile int g_flag[128];
__device__ int          g_aggv[128];
__device__ int          g_inclv[128];

// ---------------- K1: weighted in-degree + histogram + x->fp16 convert ------
__global__ void deg_conv_kernel(const float* __restrict__ x,
                                const int* __restrict__ ei,
                                const float* __restrict__ ew, int E, int n) {
    int i = blockIdx.x * blockDim.x + threadIdx.x;
    if (i < E) {
        int c = ei[E + i];
        atomicAdd(&g_deg[c], ew[i]);
        atomicAdd(&g_cnt[c], 1);
    }
    int q = n * 32;                               // float4 count
    int stride = gridDim.x * blockDim.x;
    for (int idx = i; idx < q; idx += stride) {
        float4 v = ((const float4*)x)[idx];
        __half2 h0 = __floats2half2_rn(v.x, v.y);
        __half2 h1 = __floats2half2_rn(v.z, v.w);
        uint2 u;
        u.x = *(unsigned int*)&h0;
        u.y = *(unsigned int*)&h1;
        ((uint2*)g_xh)[idx] = u;
    }
}

// ---------------- K2: dinv + single-pass exclusive scan (lookback) ----------
__global__ __launch_bounds__(SCAN_B) void scan_dinv_kernel(int n) {
    __shared__ int s[SCAN_B];
    __shared__ int s_pfx;
    int tid = threadIdx.x, b = blockIdx.x;
    int i = b * SCAN_B + tid;
    int v = (i < n) ? g_cnt[i] : 0;
    if (i < n) g_dinv[i] = rsqrtf(g_deg[i] + 1.0f);   // self-loop => deg>0
    s[tid] = v;
    __syncthreads();
    #pragma unroll
    for (int off = 1; off < SCAN_B; off <<= 1) {
        int t = (tid >= off) ? s[tid - off] : 0;
        __syncthreads();
        s[tid] += t;
        __syncthreads();
    }
    int incl  = s[tid];
    int total = s[SCAN_B - 1];
    if (tid == 0) {
        g_aggv[b] = total;
        __threadfence();
        g_flag[b] = 1;
        int pfx = 0;
        if (b > 0) {
            int j = b - 1;
            while (1) {
                int f;
                do { f = g_flag[j]; } while (f == 0);
                __threadfence();
                if (f == 2) { pfx += *((volatile int*)&g_inclv[j]); break; }
                pfx += *((volatile int*)&g_aggv[j]);
                j--;
                if (j < 0) break;
            }
        }
        g_inclv[b] = pfx + total;
        __threadfence();
        g_flag[b] = 2;
        s_pfx = pfx;
    }
    __syncthreads();
    if (i < n) {
        int st = s_pfx + incl - v;
        g_start[i]  = st;
        g_cursor[i] = st;
    }
}

// ---------------- K3: build CSR (by target) + reset scan flags --------------
__global__ void csr_kernel(const int* __restrict__ ei, const float* __restrict__ ew, int E) {
    if (blockIdx.x == 0 && threadIdx.x < 128) g_flag[threadIdx.x] = 0;  // restore invariant
    int e = blockIdx.x * blockDim.x + threadIdx.x;
    if (e >= E) return;
    int r = ei[e];
    int c = ei[E + e];
    float coef = g_dinv[r] * ew[e] * g_dinv[c];
    int pos = atomicAdd(&g_cursor[c], 1);
    g_csr[pos] = make_float2(__int_as_float(r), coef);
}

// ---------------- K4: pull gather, half-warp per node, 8-way unroll ---------
__device__ __forceinline__ void fma_edge8(float4& a, float4& b, float coef, uint4 raw) {
    __half2 h0 = *(__half2*)&raw.x;
    __half2 h1 = *(__half2*)&raw.y;
    __half2 h2 = *(__half2*)&raw.z;
    __half2 h3 = *(__half2*)&raw.w;
    float2 f0 = __half22float2(h0);
    float2 f1 = __half22float2(h1);
    float2 f2 = __half22float2(h2);
    float2 f3 = __half22float2(h3);
    a.x += coef * f0.x;  a.y += coef * f0.y;
    a.z += coef * f1.x;  a.w += coef * f1.y;
    b.x += coef * f2.x;  b.y += coef * f2.y;
    b.z += coef * f3.x;  b.w += coef * f3.y;
}

__global__ __launch_bounds__(256) void gather_kernel(int n) {
    int node = (blockIdx.x * blockDim.x + threadIdx.x) >> 4;
    int lane = threadIdx.x & 15;
    if (node >= n) return;

    const uint4* xh4 = (const uint4*)g_xh;    // 16 uint4 per row
    int start = g_start[node];
    int cnt   = g_cnt[node];
    float d   = g_dinv[node];
    if (lane == 0) { g_deg[node] = 0.f; g_cnt[node] = 0; }   // restore invariant

    // self-loop from fp16 x (keeps gather kernel off the 51MB fp32 array)
    float4 accA  = make_float4(0.f, 0.f, 0.f, 0.f);
    float4 accB  = make_float4(0.f, 0.f, 0.f, 0.f);
    float4 accA2 = make_float4(0.f, 0.f, 0.f, 0.f);
    float4 accB2 = make_float4(0.f, 0.f, 0.f, 0.f);
    {
        uint4 xs = xh4[(size_t)node * 16 + lane];
        fma_edge8(accA, accB, d * d, xs);
    }

    const float2* cs = g_csr + start;
    int e = 0;
    for (; e + 7 < cnt; e += 8) {
        float2 a0 = __ldcs(&cs[e]);
        float2 a1 = __ldcs(&cs[e + 1]);
        float2 a2 = __ldcs(&cs[e + 2]);
        float2 a3 = __ldcs(&cs[e + 3]);
        float2 a4 = __ldcs(&cs[e + 4]);
        float2 a5 = __ldcs(&cs[e + 5]);
        float2 a6 = __ldcs(&cs[e + 6]);
        float2 a7 = __ldcs(&cs[e + 7]);
        uint4 v0 = xh4[(size_t)__float_as_int(a0.x) * 16 + lane];
        uint4 v1 = xh4[(size_t)__float_as_int(a1.x) * 16 + lane];
        uint4 v2 = xh4[(size_t)__float_as_int(a2.x) * 16 + lane];
        uint4 v3 = xh4[(size_t)__float_as_int(a3.x) * 16 + lane];
        uint4 v4 = xh4[(size_t)__float_as_int(a4.x) * 16 + lane];
        uint4 v5 = xh4[(size_t)__float_as_int(a5.x) * 16 + lane];
        uint4 v6 = xh4[(size_t)__float_as_int(a6.x) * 16 + lane];
        uint4 v7 = xh4[(size_t)__float_as_int(a7.x) * 16 + lane];
        fma_edge8(accA,  accB,  a0.y, v0);
        fma_edge8(accA2, accB2, a1.y, v1);
        fma_edge8(accA,  accB,  a2.y, v2);
        fma_edge8(accA2, accB2, a3.y, v3);
        fma_edge8(accA,  accB,  a4.y, v4);
        fma_edge8(accA2, accB2, a5.y, v5);
        fma_edge8(accA,  accB,  a6.y, v6);
        fma_edge8(accA2, accB2, a7.y, v7);
    }
    for (; e + 1 < cnt; e += 2) {
        float2 a0 = __ldcs(&cs[e]);
        float2 a1 = __ldcs(&cs[e + 1]);
        uint4 v0 = xh4[(size_t)__float_as_int(a0.x) * 16 + lane];
        uint4 v1 = xh4[(size_t)__float_as_int(a1.x) * 16 + lane];
        fma_edge8(accA,  accB,  a0.y, v0);
        fma_edge8(accA2, accB2, a1.y, v1);
    }
    if (e < cnt) {
        float2 a0 = __ldcs(&cs[e]);
        uint4 v0 = xh4[(size_t)__float_as_int(a0.x) * 16 + lane];
        fma_edge8(accA, accB, a0.y, v0);
    }
    accA.x += accA2.x; accA.y += accA2.y; accA.z += accA2.z; accA.w += accA2.w;
    accB.x += accB2.x; accB.y += accB2.y; accB.z += accB2.z; accB.w += accB2.w;

    // store agg as fp16 (streaming: written once, read once by GEMM)
    __half2 h0 = __floats2half2_rn(accA.x, accA.y);
    __half2 h1 = __floats2half2_rn(accA.z, accA.w);
    __half2 h2 = __floats2half2_rn(accB.x, accB.y);
    __half2 h3 = __floats2half2_rn(accB.z, accB.w);
    uint4 u;
    u.x = *(unsigned int*)&h0;
    u.y = *(unsigned int*)&h1;
    u.z = *(unsigned int*)&h2;
    u.w = *(unsigned int*)&h3;
    __stcs(&((uint4*)g_aggh)[(size_t)node * 16 + lane], u);
}

// ---------------- K5: tensor-core GEMM + bias/relu/segment-max pool ---------
#define A_LDH 136                     // halves per row (pad 16B)
#define C_LDF 132                     // floats per row (pad 16B)
__global__ __launch_bounds__(256, 2) void gemm_pool_tc_kernel(
        const float* __restrict__ w,       // [128,128] fp32
        const float* __restrict__ bias,    // [128]
        const int*   __restrict__ batch,
        int n) {
    extern __shared__ char smraw[];
    __half* Ah = (__half*)smraw;                 // 128*136 halves
    __half* Wh = Ah + 128 * A_LDH;               // 128*136 halves
    float*  Cs = (float*)smraw;                  // overlay: 128*132 floats
    __shared__ unsigned int sp[4 * 128];         // block-local pool

    int tid = threadIdx.x;
    int wid = tid >> 5;
    int lane = tid & 31;
    int row0 = blockIdx.x * 128;

    for (int i = tid; i < 512; i += 256) sp[i] = 0u;

    // stage A rows (fp16, 16 uint4 per row)
    {
        const uint4* a4 = (const uint4*)g_aggh;
        #pragma unroll
        for (int i = tid; i < 2048; i += 256) {
            int rr = i >> 4, kq = i & 15;
            int gr = row0 + rr;
            uint4 v = make_uint4(0u, 0u, 0u, 0u);
            if (gr < n) v = a4[(size_t)gr * 16 + kq];
            *(uint4*)((char*)(Ah + rr * A_LDH) + kq * 16) = v;
        }
    }
    // stage W, converting fp32 -> fp16 (128x128)
    {
        const float4* w4 = (const float4*)w;
        #pragma unroll
        for (int i = tid; i < 4096; i += 256) {
            int k = i >> 5, q = i & 31;
            float4 v = w4[i];
            __half2 h0 = __floats2half2_rn(v.x, v.y);
            __half2 h1 = __floats2half2_rn(v.z, v.w);
            uint2 u;
            u.x = *(unsigned int*)&h0;
            u.y = *(unsigned int*)&h1;
            *(uint2*)((char*)(Wh + k * A_LDH) + q * 8) = u;
        }
    }
    __syncthreads();

    // wmma: each warp computes a 16x128 strip (8 n-tiles), k-loop of 8
    wmma::fragment<wmma::accumulator, 16, 16, 16, float> c[8];
    #pragma unroll
    for (int nt = 0; nt < 8; nt++) wmma::fill_fragment(c[nt], 0.f);

    int r0 = wid * 16;
    #pragma unroll
    for (int k = 0; k < 8; k++) {
        wmma::fragment<wmma::matrix_a, 16, 16, 16, __half, wmma::row_major> a;
        wmma::load_matrix_sync(a, Ah + r0 * A_LDH + k * 16, A_LDH);
        #pragma unroll
        for (int nt = 0; nt < 8; nt++) {
            wmma::fragment<wmma::matrix_b, 16, 16, 16, __half, wmma::row_major> b;
            wmma::load_matrix_sync(b, Wh + (k * 16) * A_LDH + nt * 16, A_LDH);
            wmma::mma_sync(c[nt], a, b, c[nt]);
        }
    }
    __syncthreads();          // all warps done reading Ah/Wh before C overlay

    #pragma unroll
    for (int nt = 0; nt < 8; nt++)
        wmma::store_matrix_sync(Cs + r0 * C_LDF + nt * 16, c[nt], C_LDF,
                                wmma::mem_row_major);
    __syncwarp();             // warp reads back only its own strip

    // epilogue: bias + relu + segment-max over this warp's 16 rows
    int c0 = lane * 4;
    float bb[4];
    #pragma unroll
    for (int j = 0; j < 4; j++) bb[j] = bias[c0 + j];

    int g_lo = batch[row0];
    int prevg = -1;
    float m[4];
    #pragma unroll
    for (int j = 0; j < 4; j++) m[j] = 0.f;

    #define EMIT_SEG4(gseg)                                                    \
        do {                                                                   \
            int s_ = (gseg) - g_lo;                                            \
            if (s_ < 4) {                                                      \
                _Pragma("unroll")                                              \
                for (int j = 0; j < 4; j++)                                    \
                    atomicMax(&sp[s_ * 128 + c0 + j], __float_as_uint(m[j]));  \
            } else {                                                           \
                _Pragma("unroll")                                              \
                for (int j = 0; j < 4; j++)                                    \
                    atomicMax(&g_pool[(gseg) * F + c0 + j], __float_as_uint(m[j])); \
            }                                                                  \
        } while (0)

    for (int i = 0; i < 16; i++) {
        int gr = row0 + r0 + i;
        if (gr >= n) break;
        int g = batch[gr];
        float v[4];
        #pragma unroll
        for (int j = 0; j < 4; j++)
            v[j] = fmaxf(Cs[(r0 + i) * C_LDF + c0 + j] + bb[j], 0.f);
        if (g != prevg) {
            if (prevg >= 0) EMIT_SEG4(prevg);
            prevg = g;
            #pragma unroll
            for (int j = 0; j < 4; j++) m[j] = v[j];
        } else {
            #pragma unroll
            for (int j = 0; j < 4; j++) m[j] = fmaxf(m[j], v[j]);
        }
    }
    if (prevg >= 0) EMIT_SEG4(prevg);
    __syncthreads();

    // flush local pool (skip zeros: relu >= 0 and global pool init is 0)
    for (int i = tid; i < 512; i += 256) {
        unsigned int v = sp[i];
        if (v) {
            int s = i >> 7, j = i & 127;
            atomicMax(&g_pool[(g_lo + s) * F + j], v);
        }
    }
}

// ---------------- K6: fused MLP head (one block) + pool reset ---------------
__global__ __launch_bounds__(1024) void head_kernel(
        const float* __restrict__ w1, const float* __restrict__ b1,
        const float* __restrict__ w2, const float* __restrict__ b2,
        float* __restrict__ out) {
    __shared__ float t1s[NUM_GRAPHS * LIN_H];   // 16KB
    int tid = threadIdx.x;
    for (int idx = tid; idx < NUM_GRAPHS * LIN_H; idx += 1024) {
        int g = idx >> 6, j = idx & 63;
        float s = b1[j];
        #pragma unroll 8
        for (int k = 0; k < F; k++)
            s += __uint_as_float(g_pool[g * F + k]) * w1[k * LIN_H + j];
        t1s[idx] = fmaxf(s, 0.f);
    }
    __syncthreads();
    for (int idx = tid; idx < NUM_GRAPHS * F; idx += 1024)   // restore invariant
        g_pool[idx] = 0u;
    for (int idx = tid; idx < NUM_GRAPHS * N_CLASSES; idx += 1024) {
        int g = idx / N_CLASSES, c = idx % N_CLASSES;
        float s = b2[c];
        #pragma unroll 8
        for (int j = 0; j < LIN_H; j++)
            s += t1s[g * LIN_H + j] * w2[j * N_CLASSES + c];
        out[idx] = s;
    }
}

// ---------------- launch ----------------------------------------------------
extern "C" void kernel_launch(void* const* d_in, const int* in_sizes, int n_in,
                              void* d_out, int out_size) {
    const float* x      = (const float*)d_in[0];
    const int*   ei     = (const int*)d_in[1];
    const float* ew     = (const float*)d_in[2];
    const int*   batch  = (const int*)d_in[3];
    const float* conv_w = (const float*)d_in[4];
    const float* conv_b = (const float*)d_in[5];
    const float* lin1_w = (const float*)d_in[6];
    const float* lin1_b = (const float*)d_in[7];
    const float* lin2_w = (const float*)d_in[8];
    const float* lin2_b = (const float*)d_in[9];
    float* out = (float*)d_out;

    int E = in_sizes[2];
    int n = in_sizes[3];
    int nscan = (n + SCAN_B - 1) / SCAN_B;

    const int smem_gemm = 2 * 128 * A_LDH * (int)sizeof(__half);   // 69632B
    cudaFuncSetAttribute(gemm_pool_tc_kernel,
                         cudaFuncAttributeMaxDynamicSharedMemorySize, smem_gemm);

    deg_conv_kernel<<<(E + 255) / 256, 256>>>(x, ei, ew, E, n);
    scan_dinv_kernel<<<nscan, SCAN_B>>>(n);
    csr_kernel<<<(E + 255) / 256, 256>>>(ei, ew, E);
    gather_kernel<<<(n + 15) / 16, 256>>>(n);                   // profiled slot #4
    gemm_pool_tc_kernel<<<(n + 127) / 128, 256, smem_gemm>>>(conv_w, conv_b, batch, n);
    head_kernel<<<1, 1024>>>(lin1_w, lin1_b, lin2_w, lin2_b, out);
}

// round 16
// speedup vs baseline: 1.6340x; 1.0510x over previous
#include <cuda_runtime.h>
#include <cuda_fp16.h>
#include <mma.h>
#include <cstdint>

using namespace nvcuda;

// Problem constants (shapes fixed by the dataset)
#define N_NODES_MAX 100096
#define E_MAX       1600000
#define F 128
#define LIN_H 64
#define N_CLASSES 10
#define NUM_GRAPHS 64
#define SCAN_B 1024
#define MASK40 ((1ull << 40) - 1ull)

// ---------------- scratch (device globals; zero-initialized at load) --------
// Self-restoring invariant: g_packed / g_flag / g_pool return to zero by the
// end of every kernel_launch call, so graph replays are deterministic.
__device__ unsigned long long g_packed[N_NODES_MAX];   // cnt<<40 | Q32 deg
__device__ int          g_cnt[N_NODES_MAX];            // written by scan each call
__device__ int          g_start[N_NODES_MAX];
__device__ int          g_cursor[N_NODES_MAX];
__device__ float        g_dinv[N_NODES_MAX];
__device__ float2       g_csr[E_MAX];                  // (src as int bits, coef)
__device__ __half       g_xh[(size_t)N_NODES_MAX * F]; // 25.6 MB fp16 copy of x
__device__ __half       g_aggh[(size_t)N_NODES_MAX * F]; // 25.6 MB fp16 agg
__device__ __half       g_wh[F * F];                   // fp16 conv_w
__device__ unsigned int g_pool[NUM_GRAPHS * F];        // float-as-uint max
// decoupled-lookback scan state
__device__ volatile int g_flag[128];
__device__ int          g_aggv[128];
__device__ int          g_inclv[128];

// ---------------- K1: packed histogram + x->fp16 + W->fp16 ------------------
__global__ void deg_conv_kernel(const float* __restrict__ x,
                                const int* __restrict__ ei,
                                const float* __restrict__ ew,
                                const float* __restrict__ conv_w, int E, int n) {
    int i = blockIdx.x * blockDim.x + threadIdx.x;
    if (i < E) {
        int c = ei[E + i];
        // one 64-bit atomic: count in [40:64), Q32 fixed-point weight in [0:40)
        unsigned long long val = (1ull << 40)
                               | (unsigned long long)(ew[i] * 4294967296.0f);
        atomicAdd(&g_packed[c], val);
    }
    // W fp32 -> fp16 (once, 2048 uint4)
    if (i < 2048) {
        const float4* w4 = (const float4*)conv_w;
        float4 v0 = w4[2 * i];
        float4 v1 = w4[2 * i + 1];
        __half2 h0 = __floats2half2_rn(v0.x, v0.y);
        __half2 h1 = __floats2half2_rn(v0.z, v0.w);
        __half2 h2 = __floats2half2_rn(v1.x, v1.y);
        __half2 h3 = __floats2half2_rn(v1.z, v1.w);
        uint4 u;
        u.x = *(unsigned int*)&h0;
        u.y = *(unsigned int*)&h1;
        u.z = *(unsigned int*)&h2;
        u.w = *(unsigned int*)&h3;
        ((uint4*)g_wh)[i] = u;
    }
    // x fp32 -> fp16, grid-stride
    int q = n * 32;
    int stride = gridDim.x * blockDim.x;
    for (int idx = i; idx < q; idx += stride) {
        float4 v = ((const float4*)x)[idx];
        __half2 h0 = __floats2half2_rn(v.x, v.y);
        __half2 h1 = __floats2half2_rn(v.z, v.w);
        uint2 u;
        u.x = *(unsigned int*)&h0;
        u.y = *(unsigned int*)&h1;
        ((uint2*)g_xh)[idx] = u;
    }
}

// ---------------- K2: dinv + single-pass exclusive scan (lookback) ----------
__global__ __launch_bounds__(SCAN_B) void scan_dinv_kernel(int n) {
    __shared__ int s[SCAN_B];
    __shared__ int s_pfx;
    int tid = threadIdx.x, b = blockIdx.x;
    int i = b * SCAN_B + tid;
    int v = 0;
    if (i < n) {
        unsigned long long p = g_packed[i];
        v = (int)(p >> 40);
        float deg = (float)(p & MASK40) * 2.3283064365386963e-10f;  // /2^32
        g_dinv[i] = rsqrtf(deg + 1.0f);   // self-loop => deg+1 > 0
        g_cnt[i]  = v;
    }
    s[tid] = v;
    __syncthreads();
    #pragma unroll
    for (int off = 1; off < SCAN_B; off <<= 1) {
        int t = (tid >= off) ? s[tid - off] : 0;
        __syncthreads();
        s[tid] += t;
        __syncthreads();
    }
    int incl  = s[tid];
    int total = s[SCAN_B - 1];
    if (tid == 0) {
        g_aggv[b] = total;
        __threadfence();
        g_flag[b] = 1;
        int pfx = 0;
        if (b > 0) {
            int j = b - 1;
            while (1) {
                int f;
                do { f = g_flag[j]; } while (f == 0);
                __threadfence();
                if (f == 2) { pfx += *((volatile int*)&g_inclv[j]); break; }
                pfx += *((volatile int*)&g_aggv[j]);
                j--;
                if (j < 0) break;
            }
        }
        g_inclv[b] = pfx + total;
        __threadfence();
        g_flag[b] = 2;
        s_pfx = pfx;
    }
    __syncthreads();
    if (i < n) {
        int st = s_pfx + incl - v;
        g_start[i]  = st;
        g_cursor[i] = st;
    }
}

// ---------------- K3: build CSR (by target) + reset scan flags --------------
__global__ void csr_kernel(const int* __restrict__ ei, const float* __restrict__ ew, int E) {
    if (blockIdx.x == 0 && threadIdx.x < 128) g_flag[threadIdx.x] = 0;  // restore invariant
    int e = blockIdx.x * blockDim.x + threadIdx.x;
    if (e >= E) return;
    int r = ei[e];
    int c = ei[E + e];
    float coef = g_dinv[r] * ew[e] * g_dinv[c];
    int pos = atomicAdd(&g_cursor[c], 1);
    g_csr[pos] = make_float2(__int_as_float(r), coef);
}

// ---------------- K4: pull gather, half-warp per node, 8-way unroll ---------
// (identical to the measured R12 gather, 62.5us; only the invariant reset
//  changed: g_packed instead of g_deg/g_cnt)
__device__ __forceinline__ void fma_edge8(float4& a, float4& b, float coef, uint4 raw) {
    __half2 h0 = *(__half2*)&raw.x;
    __half2 h1 = *(__half2*)&raw.y;
    __half2 h2 = *(__half2*)&raw.z;
    __half2 h3 = *(__half2*)&raw.w;
    float2 f0 = __half22float2(h0);
    float2 f1 = __half22float2(h1);
    float2 f2 = __half22float2(h2);
    float2 f3 = __half22float2(h3);
    a.x += coef * f0.x;  a.y += coef * f0.y;
    a.z += coef * f1.x;  a.w += coef * f1.y;
    b.x += coef * f2.x;  b.y += coef * f2.y;
    b.z += coef * f3.x;  b.w += coef * f3.y;
}

__global__ __launch_bounds__(256) void gather_kernel(int n) {
    int node = (blockIdx.x * blockDim.x + threadIdx.x) >> 4;
    int lane = threadIdx.x & 15;
    if (node >= n) return;

    const uint4* xh4 = (const uint4*)g_xh;    // 16 uint4 per row
    int start = g_start[node];
    int cnt   = g_cnt[node];
    float d   = g_dinv[node];
    if (lane == 0) g_packed[node] = 0ull;     // restore invariant

    float4 accA  = make_float4(0.f, 0.f, 0.f, 0.f);
    float4 accB  = make_float4(0.f, 0.f, 0.f, 0.f);
    float4 accA2 = make_float4(0.f, 0.f, 0.f, 0.f);
    float4 accB2 = make_float4(0.f, 0.f, 0.f, 0.f);
    {   // self-loop from fp16 x
        uint4 xs = xh4[(size_t)node * 16 + lane];
        fma_edge8(accA, accB, d * d, xs);
    }

    const float2* cs = g_csr + start;
    int e = 0;
    for (; e + 7 < cnt; e += 8) {
        float2 a0 = __ldcs(&cs[e]);
        float2 a1 = __ldcs(&cs[e + 1]);
        float2 a2 = __ldcs(&cs[e + 2]);
        float2 a3 = __ldcs(&cs[e + 3]);
        float2 a4 = __ldcs(&cs[e + 4]);
        float2 a5 = __ldcs(&cs[e + 5]);
        float2 a6 = __ldcs(&cs[e + 6]);
        float2 a7 = __ldcs(&cs[e + 7]);
        uint4 v0 = xh4[(size_t)__float_as_int(a0.x) * 16 + lane];
        uint4 v1 = xh4[(size_t)__float_as_int(a1.x) * 16 + lane];
        uint4 v2 = xh4[(size_t)__float_as_int(a2.x) * 16 + lane];
        uint4 v3 = xh4[(size_t)__float_as_int(a3.x) * 16 + lane];
        uint4 v4 = xh4[(size_t)__float_as_int(a4.x) * 16 + lane];
        uint4 v5 = xh4[(size_t)__float_as_int(a5.x) * 16 + lane];
        uint4 v6 = xh4[(size_t)__float_as_int(a6.x) * 16 + lane];
        uint4 v7 = xh4[(size_t)__float_as_int(a7.x) * 16 + lane];
        fma_edge8(accA,  accB,  a0.y, v0);
        fma_edge8(accA2, accB2, a1.y, v1);
        fma_edge8(accA,  accB,  a2.y, v2);
        fma_edge8(accA2, accB2, a3.y, v3);
        fma_edge8(accA,  accB,  a4.y, v4);
        fma_edge8(accA2, accB2, a5.y, v5);
        fma_edge8(accA,  accB,  a6.y, v6);
        fma_edge8(accA2, accB2, a7.y, v7);
    }
    for (; e + 1 < cnt; e += 2) {
        float2 a0 = __ldcs(&cs[e]);
        float2 a1 = __ldcs(&cs[e + 1]);
        uint4 v0 = xh4[(size_t)__float_as_int(a0.x) * 16 + lane];
        uint4 v1 = xh4[(size_t)__float_as_int(a1.x) * 16 + lane];
        fma_edge8(accA,  accB,  a0.y, v0);
        fma_edge8(accA2, accB2, a1.y, v1);
    }
    if (e < cnt) {
        float2 a0 = __ldcs(&cs[e]);
        uint4 v0 = xh4[(size_t)__float_as_int(a0.x) * 16 + lane];
        fma_edge8(accA, accB, a0.y, v0);
    }
    accA.x += accA2.x; accA.y += accA2.y; accA.z += accA2.z; accA.w += accA2.w;
    accB.x += accB2.x; accB.y += accB2.y; accB.z += accB2.z; accB.w += accB2.w;

    // store agg as fp16 (streaming: written once, read once by GEMM)
    __half2 h0 = __floats2half2_rn(accA.x, accA.y);
    __half2 h1 = __floats2half2_rn(accA.z, accA.w);
    __half2 h2 = __floats2half2_rn(accB.x, accB.y);
    __half2 h3 = __floats2half2_rn(accB.z, accB.w);
    uint4 u;
    u.x = *(unsigned int*)&h0;
    u.y = *(unsigned int*)&h1;
    u.z = *(unsigned int*)&h2;
    u.w = *(unsigned int*)&h3;
    __stcs(&((uint4*)g_aggh)[(size_t)node * 16 + lane], u);
}

// ---------------- K5: tensor-core GEMM + bias/relu/segment-max pool ---------
#define A_LDH 136                     // halves per row (pad 16B)
#define C_LDF 132                     // floats per row (pad 16B)
__global__ __launch_bounds__(256, 2) void gemm_pool_tc_kernel(
        const float* __restrict__ bias,    // [128]
        const int*   __restrict__ batch,
        int n) {
    extern __shared__ char smraw[];
    __half* Ah = (__half*)smraw;                 // 128*136 halves
    __half* Wh = Ah + 128 * A_LDH;               // 128*136 halves
    float*  Cs = (float*)smraw;                  // overlay: 128*132 floats
    __shared__ unsigned int sp[4 * 128];         // block-local pool

    int tid = threadIdx.x;
    int wid = tid >> 5;
    int lane = tid & 31;
    int row0 = blockIdx.x * 128;

    for (int i = tid; i < 512; i += 256) sp[i] = 0u;

    // stage A rows (fp16, 16 uint4 per row)
    {
        const uint4* a4 = (const uint4*)g_aggh;
        #pragma unroll
        for (int i = tid; i < 2048; i += 256) {
            int rr = i >> 4, kq = i & 15;
            int gr = row0 + rr;
            uint4 v = make_uint4(0u, 0u, 0u, 0u);
            if (gr < n) v = a4[(size_t)gr * 16 + kq];
            *(uint4*)((char*)(Ah + rr * A_LDH) + kq * 16) = v;
        }
    }
    // stage pre-converted fp16 W
    {
        const uint4* wh4 = (const uint4*)g_wh;
        #pragma unroll
        for (int i = tid; i < 2048; i += 256) {
            int k = i >> 4, q = i & 15;
            *(uint4*)((char*)(Wh + k * A_LDH) + q * 16) = wh4[i];
        }
    }
    __syncthreads();

    // wmma: each warp computes a 16x128 strip (8 n-tiles), k-loop of 8
    wmma::fragment<wmma::accumulator, 16, 16, 16, float> c[8];
    #pragma unroll
    for (int nt = 0; nt < 8; nt++) wmma::fill_fragment(c[nt], 0.f);

    int r0 = wid * 16;
    #pragma unroll
    for (int k = 0; k < 8; k++) {
        wmma::fragment<wmma::matrix_a, 16, 16, 16, __half, wmma::row_major> a;
        wmma::load_matrix_sync(a, Ah + r0 * A_LDH + k * 16, A_LDH);
        #pragma unroll
        for (int nt = 0; nt < 8; nt++) {
            wmma::fragment<wmma::matrix_b, 16, 16, 16, __half, wmma::row_major> b;
            wmma::load_matrix_sync(b, Wh + (k * 16) * A_LDH + nt * 16, A_LDH);
            wmma::mma_sync(c[nt], a, b, c[nt]);
        }
    }
    __syncthreads();          // all warps done reading Ah/Wh before C overlay

    #pragma unroll
    for (int nt = 0; nt < 8; nt++)
        wmma::store_matrix_sync(Cs + r0 * C_LDF + nt * 16, c[nt], C_LDF,
                                wmma::mem_row_major);
    __syncwarp();             // warp reads back only its own strip

    // epilogue: bias + relu + segment-max over this warp's 16 rows
    int c0 = lane * 4;
    float bb[4];
    #pragma unroll
    for (int j = 0; j < 4; j++) bb[j] = bias[c0 + j];

    int g_lo = batch[row0];
    int prevg = -1;
    float m[4];
    #pragma unroll
    for (int j = 0; j < 4; j++) m[j] = 0.f;

    #define EMIT_SEG4(gseg)                                                    \
        do {                                                                   \
            int s_ = (gseg) - g_lo;                                            \
            if (s_ < 4) {                                                      \
                _Pragma("unroll")                                              \
                for (int j = 0; j < 4; j++)                                    \
                    atomicMax(&sp[s_ * 128 + c0 + j], __float_as_uint(m[j]));  \
            } else {                                                           \
                _Pragma("unroll")                                              \
                for (int j = 0; j < 4; j++)                                    \
                    atomicMax(&g_pool[(gseg) * F + c0 + j], __float_as_uint(m[j])); \
            }                                                                  \
        } while (0)

    for (int i = 0; i < 16; i++) {
        int gr = row0 + r0 + i;
        if (gr >= n) break;
        int g = batch[gr];
        float v[4];
        #pragma unroll
        for (int j = 0; j < 4; j++)
            v[j] = fmaxf(Cs[(r0 + i) * C_LDF + c0 + j] + bb[j], 0.f);
        if (g != prevg) {
            if (prevg >= 0) EMIT_SEG4(prevg);
            prevg = g;
            #pragma unroll
            for (int j = 0; j < 4; j++) m[j] = v[j];
        } else {
            #pragma unroll
            for (int j = 0; j < 4; j++) m[j] = fmaxf(m[j], v[j]);
        }
    }
    if (prevg >= 0) EMIT_SEG4(prevg);
    __syncthreads();

    // flush local pool (skip zeros: relu >= 0 and global pool init is 0)
    for (int i = tid; i < 512; i += 256) {
        unsigned int v = sp[i];
        if (v) {
            int s = i >> 7, j = i & 127;
            atomicMax(&g_pool[(g_lo + s) * F + j], v);
        }
    }
}

// ---------------- K6: fused MLP head (one block) + pool reset ---------------
__global__ __launch_bounds__(1024) void head_kernel(
        const float* __restrict__ w1, const float* __restrict__ b1,
        const float* __restrict__ w2, const float* __restrict__ b2,
        float* __restrict__ out) {
    __shared__ float t1s[NUM_GRAPHS * LIN_H];   // 16KB
    int tid = threadIdx.x;
    for (int idx = tid; idx < NUM_GRAPHS * LIN_H; idx += 1024) {
        int g = idx >> 6, j = idx & 63;
        float s = b1[j];
        #pragma unroll 8
        for (int k = 0; k < F; k++)
            s += __uint_as_float(g_pool[g * F + k]) * w1[k * LIN_H + j];
        t1s[idx] = fmaxf(s, 0.f);
    }
    __syncthreads();
    for (int idx = tid; idx < NUM_GRAPHS * F; idx += 1024)   // restore invariant
        g_pool[idx] = 0u;
    for (int idx = tid; idx < NUM_GRAPHS * N_CLASSES; idx += 1024) {
        int g = idx / N_CLASSES, c = idx % N_CLASSES;
        float s = b2[c];
        #pragma unroll 8
        for (int j = 0; j < LIN_H; j++)
            s += t1s[g * LIN_H + j] * w2[j * N_CLASSES + c];
        out[idx] = s;
    }
}

// ---------------- launch ----------------------------------------------------
extern "C" void kernel_launch(void* const* d_in, const int* in_sizes, int n_in,
                              void* d_out, int out_size) {
    const float* x      = (const float*)d_in[0];
    const int*   ei     = (const int*)d_in[1];
    const float* ew     = (const float*)d_in[2];
    const int*   batch  = (const int*)d_in[3];
    const float* conv_w = (const float*)d_in[4];
    const float* conv_b = (const float*)d_in[5];
    const float* lin1_w = (const float*)d_in[6];
    const float* lin1_b = (const float*)d_in[7];
    const float* lin2_w = (const float*)d_in[8];
    const float* lin2_b = (const float*)d_in[9];
    float* out = (float*)d_out;

    int E = in_sizes[2];
    int n = in_sizes[3];
    int nscan = (n + SCAN_B - 1) / SCAN_B;

    const int smem_gemm = 2 * 128 * A_LDH * (int)sizeof(__half);   // 69632B
    cudaFuncSetAttribute(gemm_pool_tc_kernel,
                         cudaFuncAttributeMaxDynamicSharedMemorySize, smem_gemm);

    deg_conv_kernel<<<(E + 255) / 256, 256>>>(x, ei, ew, conv_w, E, n);
    scan_dinv_kernel<<<nscan, SCAN_B>>>(n);
    csr_kernel<<<(E + 255) / 256, 256>>>(ei, ew, E);
    gather_kernel<<<(n + 15) / 16, 256>>>(n);                   // profiled slot #4
    gemm_pool_tc_kernel<<<(n + 127) / 128, 256, smem_gemm>>>(conv_b, batch, n);
    head_kernel<<<1, 1024>>>(lin1_w, lin1_b, lin2_w, lin2_b, out);
}

// round 17
// speedup vs baseline: 1.6930x; 1.0362x over previous
#include <cuda_runtime.h>
#include <cuda_fp16.h>
#include <mma.h>
#include <cstdint>

using namespace nvcuda;

// Problem constants (shapes fixed by the dataset)
#define N_NODES_MAX 100096
#define E_MAX       1600000
#define F 128
#define LIN_H 64
#define N_CLASSES 10
#define NUM_GRAPHS 64
#define SCAN_B 1024
#define MASK40 ((1ull << 40) - 1ull)

// ---------------- scratch (device globals; zero-initialized at load) --------
// Self-restoring invariant: g_packed / g_flag / g_pool return to zero by the
// end of every kernel_launch call, so graph replays are deterministic.
__device__ unsigned long long g_packed[N_NODES_MAX];   // cnt<<40 | Q32 deg
__device__ int          g_cnt[N_NODES_MAX];            // written by scan each call
__device__ int          g_start[N_NODES_MAX];
__device__ int          g_cursor[N_NODES_MAX];
__device__ float        g_dinv[N_NODES_MAX];
__device__ float2       g_csr[E_MAX];                  // (src as int bits, ew)
__device__ __half       g_xh[(size_t)N_NODES_MAX * F]; // 25.6 MB fp16 dinv[r]*x[r]
__device__ __half       g_aggh[(size_t)N_NODES_MAX * F]; // 25.6 MB fp16 agg
__device__ __half       g_wh[F * F];                   // fp16 conv_w
__device__ unsigned int g_pool[NUM_GRAPHS * F];        // float-as-uint max
// decoupled-lookback scan state
__device__ volatile int g_flag[128];
__device__ int          g_aggv[128];
__device__ int          g_inclv[128];

// ---------------- K1: packed histogram + W->fp16 ----------------------------
__global__ void deg_kernel(const int* __restrict__ ei,
                           const float* __restrict__ ew,
                           const float* __restrict__ conv_w, int E) {
    int i = blockIdx.x * blockDim.x + threadIdx.x;
    if (i < E) {
        int c = ei[E + i];
        // one 64-bit atomic: count in [40:64), Q32 fixed-point weight in [0:40)
        unsigned long long val = (1ull << 40)
                               | (unsigned long long)(ew[i] * 4294967296.0f);
        atomicAdd(&g_packed[c], val);
    }
    // W fp32 -> fp16 (once, 2048 uint4)
    if (i < 2048) {
        const float4* w4 = (const float4*)conv_w;
        float4 v0 = w4[2 * i];
        float4 v1 = w4[2 * i + 1];
        __half2 h0 = __floats2half2_rn(v0.x, v0.y);
        __half2 h1 = __floats2half2_rn(v0.z, v0.w);
        __half2 h2 = __floats2half2_rn(v1.x, v1.y);
        __half2 h3 = __floats2half2_rn(v1.z, v1.w);
        uint4 u;
        u.x = *(unsigned int*)&h0;
        u.y = *(unsigned int*)&h1;
        u.z = *(unsigned int*)&h2;
        u.w = *(unsigned int*)&h3;
        ((uint4*)g_wh)[i] = u;
    }
}

// ---------------- K2: dinv + single-pass exclusive scan (lookback) ----------
__global__ __launch_bounds__(SCAN_B) void scan_dinv_kernel(int n) {
    __shared__ int s[SCAN_B];
    __shared__ int s_pfx;
    int tid = threadIdx.x, b = blockIdx.x;
    int i = b * SCAN_B + tid;
    int v = 0;
    if (i < n) {
        unsigned long long p = g_packed[i];
        v = (int)(p >> 40);
        float deg = (float)(p & MASK40) * 2.3283064365386963e-10f;  // /2^32
        g_dinv[i] = rsqrtf(deg + 1.0f);   // self-loop => deg+1 > 0
        g_cnt[i]  = v;
    }
    s[tid] = v;
    __syncthreads();
    #pragma unroll
    for (int off = 1; off < SCAN_B; off <<= 1) {
        int t = (tid >= off) ? s[tid - off] : 0;
        __syncthreads();
        s[tid] += t;
        __syncthreads();
    }
    int incl  = s[tid];
    int total = s[SCAN_B - 1];
    if (tid == 0) {
        g_aggv[b] = total;
        __threadfence();
        g_flag[b] = 1;
        int pfx = 0;
        if (b > 0) {
            int j = b - 1;
            while (1) {
                int f;
                do { f = g_flag[j]; } while (f == 0);
                __threadfence();
                if (f == 2) { pfx += *((volatile int*)&g_inclv[j]); break; }
                pfx += *((volatile int*)&g_aggv[j]);
                j--;
                if (j < 0) break;
            }
        }
        g_inclv[b] = pfx + total;
        __threadfence();
        g_flag[b] = 2;
        s_pfx = pfx;
    }
    __syncthreads();
    if (i < n) {
        int st = s_pfx + incl - v;
        g_start[i]  = st;
        g_cursor[i] = st;
    }
}

// ---------------- K3: build CSR (no dinv reads) + x -> dinv*x fp16 ----------
__global__ void csr_conv_kernel(const float* __restrict__ x,
                                const int* __restrict__ ei,
                                const float* __restrict__ ew, int E, int n) {
    int i = blockIdx.x * blockDim.x + threadIdx.x;
    if (blockIdx.x == 0 && threadIdx.x < 128) g_flag[threadIdx.x] = 0;  // restore
    if (i < E) {
        int r = ei[i];
        int c = ei[E + i];
        int pos = atomicAdd(&g_cursor[c], 1);
        g_csr[pos] = make_float2(__int_as_float(r), ew[i]);   // coef applied later
    }
    // convert x -> fp16 with dinv baked in: xh[r] = dinv[r] * x[r]
    int q = n * 32;                          // float4 count
    int stride = gridDim.x * blockDim.x;
    for (int idx = i; idx < q; idx += stride) {
        float d = g_dinv[idx >> 5];          // 32 float4 per row
        float4 v = ((const float4*)x)[idx];
        __half2 h0 = __floats2half2_rn(d * v.x, d * v.y);
        __half2 h1 = __floats2half2_rn(d * v.z, d * v.w);
        uint2 u;
        u.x = *(unsigned int*)&h0;
        u.y = *(unsigned int*)&h1;
        ((uint2*)g_xh)[idx] = u;
    }
}

// ---------------- K4: pull gather, half-warp per node, 8-way unroll ---------
// acc_pre = xh[c] + sum_e ew_e * xh[r_e]   (xh already carries dinv[row])
// agg[c]  = dinv[c] * acc_pre              (single node-local scale at end)
__device__ __forceinline__ void fma_edge8(float4& a, float4& b, float coef, uint4 raw) {
    __half2 h0 = *(__half2*)&raw.x;
    __half2 h1 = *(__half2*)&raw.y;
    __half2 h2 = *(__half2*)&raw.z;
    __half2 h3 = *(__half2*)&raw.w;
    float2 f0 = __half22float2(h0);
    float2 f1 = __half22float2(h1);
    float2 f2 = __half22float2(h2);
    float2 f3 = __half22float2(h3);
    a.x += coef * f0.x;  a.y += coef * f0.y;
    a.z += coef * f1.x;  a.w += coef * f1.y;
    b.x += coef * f2.x;  b.y += coef * f2.y;
    b.z += coef * f3.x;  b.w += coef * f3.y;
}

__global__ __launch_bounds__(256) void gather_kernel(int n) {
    int node = (blockIdx.x * blockDim.x + threadIdx.x) >> 4;
    int lane = threadIdx.x & 15;
    if (node >= n) return;

    const uint4* xh4 = (const uint4*)g_xh;    // 16 uint4 per row
    int start = g_start[node];
    int cnt   = g_cnt[node];
    float d   = g_dinv[node];
    if (lane == 0) g_packed[node] = 0ull;     // restore invariant

    float4 accA  = make_float4(0.f, 0.f, 0.f, 0.f);
    float4 accB  = make_float4(0.f, 0.f, 0.f, 0.f);
    float4 accA2 = make_float4(0.f, 0.f, 0.f, 0.f);
    float4 accB2 = make_float4(0.f, 0.f, 0.f, 0.f);
    {   // self-loop: xh[node] = dinv*x; final *d makes it dinv^2 * x
        uint4 xs = xh4[(size_t)node * 16 + lane];
        fma_edge8(accA, accB, 1.0f, xs);
    }

    const float2* cs = g_csr + start;
    int e = 0;
    for (; e + 7 < cnt; e += 8) {
        float2 a0 = __ldcs(&cs[e]);
        float2 a1 = __ldcs(&cs[e + 1]);
        float2 a2 = __ldcs(&cs[e + 2]);
        float2 a3 = __ldcs(&cs[e + 3]);
        float2 a4 = __ldcs(&cs[e + 4]);
        float2 a5 = __ldcs(&cs[e + 5]);
        float2 a6 = __ldcs(&cs[e + 6]);
        float2 a7 = __ldcs(&cs[e + 7]);
        uint4 v0 = xh4[(size_t)__float_as_int(a0.x) * 16 + lane];
        uint4 v1 = xh4[(size_t)__float_as_int(a1.x) * 16 + lane];
        uint4 v2 = xh4[(size_t)__float_as_int(a2.x) * 16 + lane];
        uint4 v3 = xh4[(size_t)__float_as_int(a3.x) * 16 + lane];
        uint4 v4 = xh4[(size_t)__float_as_int(a4.x) * 16 + lane];
        uint4 v5 = xh4[(size_t)__float_as_int(a5.x) * 16 + lane];
        uint4 v6 = xh4[(size_t)__float_as_int(a6.x) * 16 + lane];
        uint4 v7 = xh4[(size_t)__float_as_int(a7.x) * 16 + lane];
        fma_edge8(accA,  accB,  a0.y, v0);
        fma_edge8(accA2, accB2, a1.y, v1);
        fma_edge8(accA,  accB,  a2.y, v2);
        fma_edge8(accA2, accB2, a3.y, v3);
        fma_edge8(accA,  accB,  a4.y, v4);
        fma_edge8(accA2, accB2, a5.y, v5);
        fma_edge8(accA,  accB,  a6.y, v6);
        fma_edge8(accA2, accB2, a7.y, v7);
    }
    for (; e + 1 < cnt; e += 2) {
        float2 a0 = __ldcs(&cs[e]);
        float2 a1 = __ldcs(&cs[e + 1]);
        uint4 v0 = xh4[(size_t)__float_as_int(a0.x) * 16 + lane];
        uint4 v1 = xh4[(size_t)__float_as_int(a1.x) * 16 + lane];
        fma_edge8(accA,  accB,  a0.y, v0);
        fma_edge8(accA2, accB2, a1.y, v1);
    }
    if (e < cnt) {
        float2 a0 = __ldcs(&cs[e]);
        uint4 v0 = xh4[(size_t)__float_as_int(a0.x) * 16 + lane];
        fma_edge8(accA, accB, a0.y, v0);
    }
    accA.x = d * (accA.x + accA2.x); accA.y = d * (accA.y + accA2.y);
    accA.z = d * (accA.z + accA2.z); accA.w = d * (accA.w + accA2.w);
    accB.x = d * (accB.x + accB2.x); accB.y = d * (accB.y + accB2.y);
    accB.z = d * (accB.z + accB2.z); accB.w = d * (accB.w + accB2.w);

    // store agg as fp16 (streaming: written once, read once by GEMM)
    __half2 h0 = __floats2half2_rn(accA.x, accA.y);
    __half2 h1 = __floats2half2_rn(accA.z, accA.w);
    __half2 h2 = __floats2half2_rn(accB.x, accB.y);
    __half2 h3 = __floats2half2_rn(accB.z, accB.w);
    uint4 u;
    u.x = *(unsigned int*)&h0;
    u.y = *(unsigned int*)&h1;
    u.z = *(unsigned int*)&h2;
    u.w = *(unsigned int*)&h3;
    __stcs(&((uint4*)g_aggh)[(size_t)node * 16 + lane], u);
}

// ---------------- K5: tensor-core GEMM + bias/relu/segment-max pool ---------
#define A_LDH 136                     // halves per row (pad 16B)
#define C_LDF 132                     // floats per row (pad 16B)
__global__ __launch_bounds__(256, 2) void gemm_pool_tc_kernel(
        const float* __restrict__ bias,    // [128]
        const int*   __restrict__ batch,
        int n) {
    extern __shared__ char smraw[];
    __half* Ah = (__half*)smraw;                 // 128*136 halves
    __half* Wh = Ah + 128 * A_LDH;               // 128*136 halves
    float*  Cs = (float*)smraw;                  // overlay: 128*132 floats
    __shared__ unsigned int sp[4 * 128];         // block-local pool

    int tid = threadIdx.x;
    int wid = tid >> 5;
    int lane = tid & 31;
    int row0 = blockIdx.x * 128;

    for (int i = tid; i < 512; i += 256) sp[i] = 0u;

    // stage A rows (fp16, 16 uint4 per row)
    {
        const uint4* a4 = (const uint4*)g_aggh;
        #pragma unroll
        for (int i = tid; i < 2048; i += 256) {
            int rr = i >> 4, kq = i & 15;
            int gr = row0 + rr;
            uint4 v = make_uint4(0u, 0u, 0u, 0u);
            if (gr < n) v = a4[(size_t)gr * 16 + kq];
            *(uint4*)((char*)(Ah + rr * A_LDH) + kq * 16) = v;
        }
    }
    // stage pre-converted fp16 W
    {
        const uint4* wh4 = (const uint4*)g_wh;
        #pragma unroll
        for (int i = tid; i < 2048; i += 256) {
            int k = i >> 4, q = i & 15;
            *(uint4*)((char*)(Wh + k * A_LDH) + q * 16) = wh4[i];
        }
    }
    __syncthreads();

    // wmma: each warp computes a 16x128 strip (8 n-tiles), k-loop of 8
    wmma::fragment<wmma::accumulator, 16, 16, 16, float> c[8];
    #pragma unroll
    for (int nt = 0; nt < 8; nt++) wmma::fill_fragment(c[nt], 0.f);

    int r0 = wid * 16;
    #pragma unroll
    for (int k = 0; k < 8; k++) {
        wmma::fragment<wmma::matrix_a, 16, 16, 16, __half, wmma::row_major> a;
        wmma::load_matrix_sync(a, Ah + r0 * A_LDH + k * 16, A_LDH);
        #pragma unroll
        for (int nt = 0; nt < 8; nt++) {
            wmma::fragment<wmma::matrix_b, 16, 16, 16, __half, wmma::row_major> b;
            wmma::load_matrix_sync(b, Wh + (k * 16) * A_LDH + nt * 16, A_LDH);
            wmma::mma_sync(c[nt], a, b, c[nt]);
        }
    }
    __syncthreads();          // all warps done reading Ah/Wh before C overlay

    #pragma unroll
    for (int nt = 0; nt < 8; nt++)
        wmma::store_matrix_sync(Cs + r0 * C_LDF + nt * 16, c[nt], C_LDF,
                                wmma::mem_row_major);
    __syncwarp();             // warp reads back only its own strip

    // epilogue: bias + relu + segment-max over this warp's 16 rows
    int c0 = lane * 4;
    float bb[4];
    #pragma unroll
    for (int j = 0; j < 4; j++) bb[j] = bias[c0 + j];

    int g_lo = batch[row0];
    int prevg = -1;
    float m[4];
    #pragma unroll
    for (int j = 0; j < 4; j++) m[j] = 0.f;

    #define EMIT_SEG4(gseg)                                                    \
        do {                                                                   \
            int s_ = (gseg) - g_lo;                                            \
            if (s_ < 4) {                                                      \
                _Pragma("unroll")                                              \
                for (int j = 0; j < 4; j++)                                    \
                    atomicMax(&sp[s_ * 128 + c0 + j], __float_as_uint(m[j]));  \
            } else {                                                           \
                _Pragma("unroll")                                              \
                for (int j = 0; j < 4; j++)                                    \
                    atomicMax(&g_pool[(gseg) * F + c0 + j], __float_as_uint(m[j])); \
            }                                                                  \
        } while (0)

    for (int i = 0; i < 16; i++) {
        int gr = row0 + r0 + i;
        if (gr >= n) break;
        int g = batch[gr];
        float v[4];
        #pragma unroll
        for (int j = 0; j < 4; j++)
            v[j] = fmaxf(Cs[(r0 + i) * C_LDF + c0 + j] + bb[j], 0.f);
        if (g != prevg) {
            if (prevg >= 0) EMIT_SEG4(prevg);
            prevg = g;
            #pragma unroll
            for (int j = 0; j < 4; j++) m[j] = v[j];
        } else {
            #pragma unroll
            for (int j = 0; j < 4; j++) m[j] = fmaxf(m[j], v[j]);
        }
    }
    if (prevg >= 0) EMIT_SEG4(prevg);
    __syncthreads();

    // flush local pool (skip zeros: relu >= 0 and global pool init is 0)
    for (int i = tid; i < 512; i += 256) {
        unsigned int v = sp[i];
        if (v) {
            int s = i >> 7, j = i & 127;
            atomicMax(&g_pool[(g_lo + s) * F + j], v);
        }
    }
}

// ---------------- K6: fused MLP head (one block) + pool reset ---------------
__global__ __launch_bounds__(1024) void head_kernel(
        const float* __restrict__ w1, const float* __restrict__ b1,
        const float* __restrict__ w2, const float* __restrict__ b2,
        float* __restrict__ out) {
    __shared__ float t1s[NUM_GRAPHS * LIN_H];   // 16KB
    int tid = threadIdx.x;
    for (int idx = tid; idx < NUM_GRAPHS * LIN_H; idx += 1024) {
        int g = idx >> 6, j = idx & 63;
        float s = b1[j];
        #pragma unroll 8
        for (int k = 0; k < F; k++)
            s += __uint_as_float(g_pool[g * F + k]) * w1[k * LIN_H + j];
        t1s[idx] = fmaxf(s, 0.f);
    }
    __syncthreads();
    for (int idx = tid; idx < NUM_GRAPHS * F; idx += 1024)   // restore invariant
        g_pool[idx] = 0u;
    for (int idx = tid; idx < NUM_GRAPHS * N_CLASSES; idx += 1024) {
        int g = idx / N_CLASSES, c = idx % N_CLASSES;
        float s = b2[c];
        #pragma unroll 8
        for (int j = 0; j < LIN_H; j++)
            s += t1s[g * LIN_H + j] * w2[j * N_CLASSES + c];
        out[idx] = s;
    }
}

// ---------------- launch ----------------------------------------------------
extern "C" void kernel_launch(void* const* d_in, const int* in_sizes, int n_in,
                              void* d_out, int out_size) {
    const float* x      = (const float*)d_in[0];
    const int*   ei     = (const int*)d_in[1];
    const float* ew     = (const float*)d_in[2];
    const int*   batch  = (const int*)d_in[3];
    const float* conv_w = (const float*)d_in[4];
    const float* conv_b = (const float*)d_in[5];
    const float* lin1_w = (const float*)d_in[6];
    const float* lin1_b = (const float*)d_in[7];
    const float* lin2_w = (const float*)d_in[8];
    const float* lin2_b = (const float*)d_in[9];
    float* out = (float*)d_out;

    int E = in_sizes[2];
    int n = in_sizes[3];
    int nscan = (n + SCAN_B - 1) / SCAN_B;

    const int smem_gemm = 2 * 128 * A_LDH * (int)sizeof(__half);   // 69632B
    cudaFuncSetAttribute(gemm_pool_tc_kernel,
                         cudaFuncAttributeMaxDynamicSharedMemorySize, smem_gemm);

    deg_kernel<<<(E + 255) / 256, 256>>>(ei, ew, conv_w, E);
    scan_dinv_kernel<<<nscan, SCAN_B>>>(n);
    csr_conv_kernel<<<(E + 255) / 256, 256>>>(x, ei, ew, E, n);
    gather_kernel<<<(n + 15) / 16, 256>>>(n);                   // profiled slot #4
    gemm_pool_tc_kernel<<<(n + 127) / 128, 256, smem_gemm>>>(conv_b, batch, n);
    head_kernel<<<1, 1024>>>(lin1_w, lin1_b, lin2_w, lin2_b, out);
}